// round 15
// baseline (speedup 1.0000x reference)
#include <cuda_runtime.h>
#include <cuda_fp16.h>
#include <math.h>

#define BD 2
#define SD 1024
#define TD (BD*SD)
#define HDIM 1024
#define HQ 16
#define HKV 4
#define HDH 64
#define ED 8
#define IDIM 2048
#define CAP (2*TD)
#define EPSF 1e-6f

// fp16 GEMM smem strides (u32 units)
#define SAH 20
#define SBH 136
#define SBHM 72
#define GEMM_SMEM ((2*128*SAH + 2*16*SBH) * 4)
#define MOE1_SMEM ((2*128*SAH + 2*2*16*SBHM) * 4)

// ---------------- scratch ----------------
__device__ __half g_hn[TD*HDIM];
__device__ float  g_q[TD*HQ*HDH];
__device__ float  g_kproj[TD*HKV*HDH];
__device__ __half g_qh[TD*HQ*HDH];
__device__ __half g_kh[TD*HKV*HDH];
__device__ __half g_vT[(size_t)BD*HKV*HDH*SD];
__device__ __half g_y[TD*HQ*HDH];
__device__ __half g_t[TD*HDIM];
__device__ __half g_gbuf[(size_t)(CAP+128)*IDIM];
__device__ int    g_cnt[ED];
__device__ int    g_base[ED];
__device__ int    g_tok[ED*CAP];
__device__ float  g_wt[ED*CAP];

// ---------------- helpers ----------------
__device__ __forceinline__ void mma_f16(float* c,
                                        unsigned a0, unsigned a1, unsigned a2, unsigned a3,
                                        unsigned b0, unsigned b1) {
    asm volatile("mma.sync.aligned.m16n8k16.row.col.f32.f16.f16.f32 "
                 "{%0,%1,%2,%3}, {%4,%5,%6,%7}, {%8,%9}, {%0,%1,%2,%3};"
                 : "+f"(c[0]), "+f"(c[1]), "+f"(c[2]), "+f"(c[3])
                 : "r"(a0), "r"(a1), "r"(a2), "r"(a3), "r"(b0), "r"(b1));
}
__device__ __forceinline__ unsigned pack2(float lo, float hi) {
    __half2 h = __floats2half2_rn(lo, hi);
    return *(unsigned*)&h;
}
__device__ __forceinline__ void cp16(const void* sdst, const void* g) {
    unsigned a = (unsigned)__cvta_generic_to_shared(sdst);
    asm volatile("cp.async.cg.shared.global [%0], [%1], 16;" :: "r"(a), "l"(g));
}
__device__ __forceinline__ void cp_commit() { asm volatile("cp.async.commit_group;"); }
__device__ __forceinline__ void cp_wait0()  { asm volatile("cp.async.wait_group 0;"); }
__device__ __forceinline__ void cp_wait1()  { asm volatile("cp.async.wait_group 1;"); }

// ---------------- RMSNorm over H=1024, half output ----------------
__global__ __launch_bounds__(256) void rmsnorm_k(const float* __restrict__ x,
                                                 const float* __restrict__ w,
                                                 __half* __restrict__ out) {
    int row = blockIdx.x;
    int tid = threadIdx.x;
    const float* xr = x + (size_t)row * HDIM;
    float4 v = *(const float4*)(xr + tid * 4);
    float ss = v.x * v.x + v.y * v.y + v.z * v.z + v.w * v.w;
#pragma unroll
    for (int o = 16; o > 0; o >>= 1) ss += __shfl_xor_sync(0xffffffffu, ss, o);
    __shared__ float sred[8];
    if ((tid & 31) == 0) sred[tid >> 5] = ss;
    __syncthreads();
    float tot = ((sred[0] + sred[1]) + (sred[2] + sred[3])) +
                ((sred[4] + sred[5]) + (sred[6] + sred[7]));
    float mean = tot * (1.0f / HDIM) + EPSF;
    float r = rsqrtf(mean);
    r = r * (1.5f - 0.5f * mean * r * r);
    float4 w4 = *(const float4*)(w + tid * 4);
    __half* orow = out + (size_t)row * HDIM + tid * 4;
    *(unsigned*)(orow)     = pack2(v.x * r * w4.x, v.y * r * w4.y);
    *(unsigned*)(orow + 2) = pack2(v.z * r * w4.z, v.w * r * w4.w);
}

// ---------------- fused RMSNorm2 + gate + routing ----------------
__global__ __launch_bounds__(256) void rmsgate_k(const float* __restrict__ x,
                                                 const float* __restrict__ w,
                                                 const float* __restrict__ gw,
                                                 __half* __restrict__ out) {
    int row = blockIdx.x;
    int tid = threadIdx.x;
    const float* xr = x + (size_t)row * HDIM;
    float4 v = *(const float4*)(xr + tid * 4);
    float ss = v.x * v.x + v.y * v.y + v.z * v.z + v.w * v.w;
#pragma unroll
    for (int o = 16; o > 0; o >>= 1) ss += __shfl_xor_sync(0xffffffffu, ss, o);
    __shared__ float sred[8];
    if ((tid & 31) == 0) sred[tid >> 5] = ss;
    __syncthreads();
    float tot = ((sred[0] + sred[1]) + (sred[2] + sred[3])) +
                ((sred[4] + sred[5]) + (sred[6] + sred[7]));
    float mean = tot * (1.0f / HDIM) + EPSF;
    float r = rsqrtf(mean);
    r = r * (1.5f - 0.5f * mean * r * r);
    float4 w4 = *(const float4*)(w + tid * 4);
    float t0 = v.x * r * w4.x, t1 = v.y * r * w4.y;
    float t2 = v.z * r * w4.z, t3 = v.w * r * w4.w;
    __half* orow = out + (size_t)row * HDIM + tid * 4;
    *(unsigned*)(orow)     = pack2(t0, t1);
    *(unsigned*)(orow + 2) = pack2(t2, t3);
    float acc[ED];
    const float* g0 = gw + (size_t)(tid * 4) * ED;
#pragma unroll
    for (int e = 0; e < ED; e++)
        acc[e] = t0 * g0[e] + t1 * g0[ED + e] + t2 * g0[2 * ED + e] + t3 * g0[3 * ED + e];
#pragma unroll
    for (int e = 0; e < ED; e++)
#pragma unroll
        for (int o = 16; o > 0; o >>= 1) acc[e] += __shfl_xor_sync(0xffffffffu, acc[e], o);
    __shared__ float sr[8][ED];
    int wid = tid >> 5, lane = tid & 31;
    if (lane == 0) {
#pragma unroll
        for (int e = 0; e < ED; e++) sr[wid][e] = acc[e];
    }
    __syncthreads();
    if (tid == 0) {
        float lg[ED];
#pragma unroll
        for (int e = 0; e < ED; e++) {
            float s = 0.f;
            for (int ww = 0; ww < 8; ww++) s += sr[ww][e];
            lg[e] = s;
        }
        int i1 = 0; float v1 = lg[0];
        for (int e = 1; e < ED; e++) if (lg[e] > v1) { v1 = lg[e]; i1 = e; }
        int i2 = -1; float v2 = -3.4e38f;
        for (int e = 0; e < ED; e++) if (e != i1 && lg[e] > v2) { v2 = lg[e]; i2 = e; }
        float bexp = __expf(v2 - v1);
        float wA = 1.f / (1.f + bexp);
        float wB = bexp / (1.f + bexp);
        int p1 = atomicAdd(&g_cnt[i1], 1);
        g_tok[i1 * CAP + p1] = row; g_wt[i1 * CAP + p1] = wA;
        int p2 = atomicAdd(&g_cnt[i2], 1);
        g_tok[i2 * CAP + p2] = row; g_wt[i2 * CAP + p2] = wB;
    }
}

// ============ fp16 GEMM core ============
__device__ __forceinline__ void h16_compute(int wm, int wn, int g, int t,
                                            unsigned (*As)[SAH], unsigned (*Bs)[SBH],
                                            float acc[4][4][4]) {
#pragma unroll
    for (int ks = 0; ks < 2; ks++) {
        int ko = ks * 8;
        unsigned af[4][4], bf[4][2];
#pragma unroll
        for (int mi = 0; mi < 4; mi++) {
            int mb = wm + mi * 16;
            af[mi][0] = As[mb + g][ko + t];
            af[mi][1] = As[mb + g + 8][ko + t];
            af[mi][2] = As[mb + g][ko + t + 4];
            af[mi][3] = As[mb + g + 8][ko + t + 4];
        }
#pragma unroll
        for (int ni = 0; ni < 4; ni++) {
            int nb = wn + ni * 8;
            bf[ni][0] = Bs[ko + t][nb + g];
            bf[ni][1] = Bs[ko + t + 4][nb + g];
        }
#pragma unroll
        for (int mi = 0; mi < 4; mi++)
#pragma unroll
            for (int ni = 0; ni < 4; ni++)
                mma_f16(acc[mi][ni], af[mi][0], af[mi][1], af[mi][2], af[mi][3],
                        bf[ni][0], bf[ni][1]);
    }
}

__device__ __forceinline__ void h16_stage_b(unsigned (*Bs)[SBH], int kb, int n0,
                                            const float4 b_st[4]) {
    uint4 u0, u1;
    u0.x = pack2(b_st[0].x, b_st[1].x); u0.y = pack2(b_st[0].y, b_st[1].y);
    u0.z = pack2(b_st[0].z, b_st[1].z); u0.w = pack2(b_st[0].w, b_st[1].w);
    u1.x = pack2(b_st[2].x, b_st[3].x); u1.y = pack2(b_st[2].y, b_st[3].y);
    u1.z = pack2(b_st[2].z, b_st[3].z); u1.w = pack2(b_st[2].w, b_st[3].w);
    *(uint4*)&Bs[kb][n0]     = u0;
    *(uint4*)&Bs[kb + 8][n0] = u1;
}

// ---------------- generic GEMM (+resid) ----------------
__global__ __launch_bounds__(256) void gemm_tc(const __half* __restrict__ A,
                                               const float* __restrict__ Bm,
                                               float* __restrict__ C,
                                               const float* __restrict__ resid,
                                               int M, int N, int K) {
    extern __shared__ unsigned dsm[];
    unsigned (*As)[128][SAH] = (unsigned(*)[128][SAH])dsm;
    unsigned (*Bs)[16][SBH]  = (unsigned(*)[16][SBH])(dsm + 2 * 128 * SAH);
    int tid = threadIdx.x, lane = tid & 31, wid = tid >> 5;
    int wm = (wid >> 2) * 64, wn = (wid & 3) * 32;
    int g = lane >> 2, t = lane & 3;
    int arow = tid >> 2, achk = (tid & 3);
    int kb = tid >> 5, n0 = (tid & 31) * 4;
    int bm = blockIdx.y, bn = blockIdx.x;
    const __half* Ag = A + (size_t)(bm * 128 + arow) * K + achk * 8;
    const __half* Ag2 = Ag + (size_t)64 * K;
    const float* Bg = Bm + bn * 128 + n0;
    cp16(&As[0][arow][achk * 4], Ag);
    cp16(&As[0][arow + 64][achk * 4], Ag2);
    cp_commit();
    float4 b_st[4];
#pragma unroll
    for (int i = 0; i < 2; i++) {
        b_st[i]     = *(const float4*)(Bg + (size_t)(2 * kb + i) * N);
        b_st[i + 2] = *(const float4*)(Bg + (size_t)(2 * kb + 16 + i) * N);
    }
    float acc[4][4][4] = {};
    int nk = K / 32;
    for (int kt = 0; kt < nk; kt++) {
        int p = kt & 1;
        cp_wait0();
        h16_stage_b(Bs[p], kb, n0, b_st);
        __syncthreads();
        if (kt + 1 < nk) {
            int ko = (kt + 1) * 32;
            cp16(&As[p ^ 1][arow][achk * 4], Ag + ko);
            cp16(&As[p ^ 1][arow + 64][achk * 4], Ag2 + ko);
            const float* Bn = Bg + (size_t)ko * N;
#pragma unroll
            for (int i = 0; i < 2; i++) {
                b_st[i]     = *(const float4*)(Bn + (size_t)(2 * kb + i) * N);
                b_st[i + 2] = *(const float4*)(Bn + (size_t)(2 * kb + 16 + i) * N);
            }
        }
        cp_commit();
        h16_compute(wm, wn, g, t, As[p], Bs[p], acc);
    }
#pragma unroll
    for (int mi = 0; mi < 4; mi++) {
#pragma unroll
        for (int ni = 0; ni < 4; ni++) {
            int row0 = bm * 128 + wm + mi * 16 + g;
            int col = bn * 128 + wn + ni * 8 + 2 * t;
            size_t o0 = (size_t)row0 * N + col;
            size_t o1 = (size_t)(row0 + 8) * N + col;
            float2 v0 = make_float2(acc[mi][ni][0], acc[mi][ni][1]);
            float2 v1 = make_float2(acc[mi][ni][2], acc[mi][ni][3]);
            if (resid) {
                float2 r0 = *(const float2*)(resid + o0);
                float2 r1 = *(const float2*)(resid + o1);
                v0.x += r0.x; v0.y += r0.y; v1.x += r1.x; v1.y += r1.y;
            }
            *(float2*)(C + o0) = v0;
            *(float2*)(C + o1) = v1;
        }
    }
}

// ---------------- fused QKV projection ----------------
__global__ __launch_bounds__(256) void qkv_tc(const __half* __restrict__ hn,
                                              const float* __restrict__ wq,
                                              const float* __restrict__ wk,
                                              const float* __restrict__ wv,
                                              float* __restrict__ qb,
                                              float* __restrict__ kp,
                                              float* __restrict__ vo) {
    extern __shared__ unsigned dsm[];
    unsigned (*As)[128][SAH] = (unsigned(*)[128][SAH])dsm;
    unsigned (*Bs)[16][SBH]  = (unsigned(*)[16][SBH])(dsm + 2 * 128 * SAH);
    int tid = threadIdx.x, lane = tid & 31, wid = tid >> 5;
    int wm = (wid >> 2) * 64, wn = (wid & 3) * 32;
    int g = lane >> 2, t = lane & 3;
    int arow = tid >> 2, achk = (tid & 3);
    int kb = tid >> 5, n0 = (tid & 31) * 4;
    int bm = blockIdx.y, bn = blockIdx.x;
    const float* Bm; float* C; int N, coff;
    if (bn < 8)       { Bm = wq; C = qb; N = 1024; coff = bn * 128; }
    else if (bn < 10) { Bm = wk; C = kp; N = 256;  coff = (bn - 8) * 128; }
    else              { Bm = wv; C = vo; N = 256;  coff = (bn - 10) * 128; }
    const __half* Ag = hn + (size_t)(bm * 128 + arow) * HDIM + achk * 8;
    const __half* Ag2 = Ag + (size_t)64 * HDIM;
    const float* Bg = Bm + coff + n0;
    cp16(&As[0][arow][achk * 4], Ag);
    cp16(&As[0][arow + 64][achk * 4], Ag2);
    cp_commit();
    float4 b_st[4];
#pragma unroll
    for (int i = 0; i < 2; i++) {
        b_st[i]     = *(const float4*)(Bg + (size_t)(2 * kb + i) * N);
        b_st[i + 2] = *(const float4*)(Bg + (size_t)(2 * kb + 16 + i) * N);
    }
    float acc[4][4][4] = {};
    const int nk = HDIM / 32;
    for (int kt = 0; kt < nk; kt++) {
        int p = kt & 1;
        cp_wait0();
        h16_stage_b(Bs[p], kb, n0, b_st);
        __syncthreads();
        if (kt + 1 < nk) {
            int ko = (kt + 1) * 32;
            cp16(&As[p ^ 1][arow][achk * 4], Ag + ko);
            cp16(&As[p ^ 1][arow + 64][achk * 4], Ag2 + ko);
            const float* Bn = Bg + (size_t)ko * N;
#pragma unroll
            for (int i = 0; i < 2; i++) {
                b_st[i]     = *(const float4*)(Bn + (size_t)(2 * kb + i) * N);
                b_st[i + 2] = *(const float4*)(Bn + (size_t)(2 * kb + 16 + i) * N);
            }
        }
        cp_commit();
        h16_compute(wm, wn, g, t, As[p], Bs[p], acc);
    }
#pragma unroll
    for (int mi = 0; mi < 4; mi++) {
#pragma unroll
        for (int ni = 0; ni < 4; ni++) {
            int row0 = bm * 128 + wm + mi * 16 + g;
            int col = coff + wn + ni * 8 + 2 * t;
            *(float2*)(C + (size_t)row0 * N + col) =
                make_float2(acc[mi][ni][0], acc[mi][ni][1]);
            *(float2*)(C + (size_t)(row0 + 8) * N + col) =
                make_float2(acc[mi][ni][2], acc[mi][ni][3]);
        }
    }
}

// ---------------- merged RMSNorm + RoPE: q -> half; k -> f32 + half ----------
__global__ __launch_bounds__(64) void qknorm_rope2_k(const float* __restrict__ qin,
                                                     const float* __restrict__ kin,
                                                     const float* __restrict__ qw,
                                                     const float* __restrict__ kw,
                                                     const float* __restrict__ freq,
                                                     __half* __restrict__ qh,
                                                     float* __restrict__ kout,
                                                     __half* __restrict__ kh) {
    int row = blockIdx.x;
    const float* in; const float* w; int nH, idx;
    bool isq;
    if (row < TD * HQ) { in = qin; w = qw; nH = HQ; idx = row; isq = true; }
    else { idx = row - TD * HQ; in = kin; w = kw; nH = HKV; isq = false; }
    int t = idx / nH;
    int s = t & (SD - 1);
    int d = threadIdx.x;
    float v = in[(size_t)idx * HDH + d];
    float ss = v * v;
#pragma unroll
    for (int o = 16; o > 0; o >>= 1) ss += __shfl_xor_sync(0xffffffffu, ss, o);
    __shared__ float sp[2];
    __shared__ float nb[HDH];
    if ((d & 31) == 0) sp[d >> 5] = ss;
    __syncthreads();
    float mean = (sp[0] + sp[1]) * (1.0f / HDH) + EPSF;
    float r = rsqrtf(mean);
    r = r * (1.5f - 0.5f * mean * r * r);
    nb[d] = v * r * w[d];
    __syncthreads();
    float o;
    if (d < 32) {
        float f = freq[s * 32 + d];
        o = nb[d] * cosf(f) - nb[d + 32] * sinf(f);
    } else {
        int j = d - 32;
        float f = freq[s * 32 + j];
        o = nb[j] * sinf(f) + nb[d] * cosf(f);
    }
    if (isq) {
        qh[(size_t)idx * HDH + d] = __float2half(o);
    } else {
        kout[(size_t)idx * HDH + d] = o;
        kh[(size_t)idx * HDH + d] = __float2half(o);
    }
}

// ---------------- V transpose: f32 [b,s,kvh,d] -> half [b,kvh,d,s] --------------
__global__ __launch_bounds__(256) void vtrans_k(const float* __restrict__ v,
                                                __half* __restrict__ vT) {
    __shared__ float sm[64][65];
    int st = blockIdx.x * 64;
    int bk = blockIdx.y;
    int b = bk >> 2, kvh = bk & 3;
    int tid = threadIdx.x;
    int s = tid >> 2, d0 = (tid & 3) * 16;
    const float* src = v + ((size_t)(b * SD + st + s) * HKV + kvh) * HDH + d0;
#pragma unroll
    for (int i = 0; i < 4; i++) {
        float4 x = *(const float4*)(src + i * 4);
        sm[s][d0 + i * 4]     = x.x; sm[s][d0 + i * 4 + 1] = x.y;
        sm[s][d0 + i * 4 + 2] = x.z; sm[s][d0 + i * 4 + 3] = x.w;
    }
    __syncthreads();
    int d = tid >> 2, s0 = (tid & 3) * 16;
    __half* dst = vT + ((size_t)bk * HDH + d) * SD + st + s0;
#pragma unroll
    for (int i = 0; i < 8; i++)
        *(unsigned*)(dst + i * 2) = pack2(sm[s0 + 2 * i][d], sm[s0 + 2 * i + 1][d]);
}

// ---------------- fp16 flash attention, 64-row Q tiles (R13), causal, GQA -------
#define AS_S 36
#define ATT_SMEM ((5*64*AS_S) * 4)

__global__ __launch_bounds__(128) void attn_h(const __half* __restrict__ q,
                                              const __half* __restrict__ k,
                                              const __half* __restrict__ vT,
                                              __half* __restrict__ y) {
    extern __shared__ unsigned smem[];
    unsigned (*Ks)[64][AS_S] = (unsigned(*)[64][AS_S])smem;
    unsigned (*Vs)[64][AS_S] = (unsigned(*)[64][AS_S])(smem + 2 * 64 * AS_S);
    unsigned (*Ps)[AS_S]     = (unsigned(*)[AS_S])(smem + 4 * 64 * AS_S);
    int qt = (SD / 64 - 1) - blockIdx.x;
    int h = blockIdx.y, b = blockIdx.z;
    int tid = threadIdx.x, lane = tid & 31, wid = tid >> 5;
    int g = lane >> 2, t = lane & 3;
    int kvh = h >> 2;
    int wq0 = wid * 16;
    const float scale = 0.125f;
    const __half* kbase = k + (size_t)kvh * HDH + (size_t)b * SD * HKV * HDH;
    const __half* vbase = vT + ((size_t)(b * HKV + kvh)) * HDH * SD;

#pragma unroll
    for (int i = 0; i < 4; i++) {
        int idx = tid + 128 * i;
        int r = idx >> 3, c = idx & 7;
        cp16(&Ps[r][c * 4], q + ((size_t)(b * SD + qt * 64 + r) * HQ + h) * HDH + c * 8);
    }
    cp_commit();
#pragma unroll
    for (int i = 0; i < 4; i++) {
        int idx = tid + 128 * i;
        int r = idx >> 3, c = idx & 7;
        cp16(&Ks[0][r][c * 4], kbase + (size_t)r * HKV * HDH + c * 8);
        cp16(&Vs[0][r][c * 4], vbase + (size_t)r * SD + c * 8);
    }
    cp_commit();
    cp_wait0();
    __syncthreads();
    unsigned qf[4][4];
#pragma unroll
    for (int ks = 0; ks < 4; ks++) {
        qf[ks][0] = Ps[wq0 + g][8 * ks + t];
        qf[ks][1] = Ps[wq0 + g + 8][8 * ks + t];
        qf[ks][2] = Ps[wq0 + g][8 * ks + t + 4];
        qf[ks][3] = Ps[wq0 + g + 8][8 * ks + t + 4];
    }
    __syncthreads();
    float m0 = -1e30f, m1 = -1e30f, l0 = 0.f, l1 = 0.f;
    float oacc[8][4] = {};

    for (int kt = 0; kt <= qt; kt++) {
        int buf = kt & 1;
        if (kt < qt) {
#pragma unroll
            for (int i = 0; i < 4; i++) {
                int idx = tid + 128 * i;
                int r = idx >> 3, c = idx & 7;
                cp16(&Ks[buf ^ 1][r][c * 4],
                     kbase + (size_t)((kt + 1) * 64 + r) * HKV * HDH + c * 8);
                cp16(&Vs[buf ^ 1][r][c * 4],
                     vbase + (size_t)r * SD + (kt + 1) * 64 + c * 8);
            }
            cp_commit();
            cp_wait1();
        } else {
            cp_wait0();
        }
        __syncthreads();
        float sacc[8][4] = {};
#pragma unroll
        for (int ks = 0; ks < 4; ks++) {
#pragma unroll
            for (int nt = 0; nt < 8; nt++) {
                unsigned b0 = Ks[buf][nt * 8 + g][8 * ks + t];
                unsigned b1 = Ks[buf][nt * 8 + g][8 * ks + t + 4];
                mma_f16(sacc[nt], qf[ks][0], qf[ks][1], qf[ks][2], qf[ks][3], b0, b1);
            }
        }
        float mx0 = -1e30f, mx1 = -1e30f;
        if (kt == qt) {
            int r0 = wq0 + g, r1 = r0 + 8;
#pragma unroll
            for (int nt = 0; nt < 8; nt++) {
                int c0 = nt * 8 + 2 * t, c1 = c0 + 1;
                sacc[nt][0] = (c0 <= r0) ? sacc[nt][0] * scale : -1e30f;
                sacc[nt][1] = (c1 <= r0) ? sacc[nt][1] * scale : -1e30f;
                sacc[nt][2] = (c0 <= r1) ? sacc[nt][2] * scale : -1e30f;
                sacc[nt][3] = (c1 <= r1) ? sacc[nt][3] * scale : -1e30f;
                mx0 = fmaxf(mx0, fmaxf(sacc[nt][0], sacc[nt][1]));
                mx1 = fmaxf(mx1, fmaxf(sacc[nt][2], sacc[nt][3]));
            }
        } else {
#pragma unroll
            for (int nt = 0; nt < 8; nt++) {
                sacc[nt][0] *= scale; sacc[nt][1] *= scale;
                sacc[nt][2] *= scale; sacc[nt][3] *= scale;
                mx0 = fmaxf(mx0, fmaxf(sacc[nt][0], sacc[nt][1]));
                mx1 = fmaxf(mx1, fmaxf(sacc[nt][2], sacc[nt][3]));
            }
        }
        mx0 = fmaxf(mx0, __shfl_xor_sync(0xffffffffu, mx0, 1));
        mx0 = fmaxf(mx0, __shfl_xor_sync(0xffffffffu, mx0, 2));
        mx1 = fmaxf(mx1, __shfl_xor_sync(0xffffffffu, mx1, 1));
        mx1 = fmaxf(mx1, __shfl_xor_sync(0xffffffffu, mx1, 2));
        float nm0 = fmaxf(m0, mx0), nm1 = fmaxf(m1, mx1);
        float corr0 = __expf(m0 - nm0), corr1 = __expf(m1 - nm1);
        m0 = nm0; m1 = nm1;
        float ls0 = 0.f, ls1 = 0.f;
#pragma unroll
        for (int nt = 0; nt < 8; nt++) {
            float p0 = __expf(sacc[nt][0] - nm0);
            float p1 = __expf(sacc[nt][1] - nm0);
            float p2 = __expf(sacc[nt][2] - nm1);
            float p3 = __expf(sacc[nt][3] - nm1);
            ls0 += p0 + p1; ls1 += p2 + p3;
            Ps[wq0 + g][nt * 4 + t]     = pack2(p0, p1);
            Ps[wq0 + g + 8][nt * 4 + t] = pack2(p2, p3);
        }
        ls0 += __shfl_xor_sync(0xffffffffu, ls0, 1);
        ls0 += __shfl_xor_sync(0xffffffffu, ls0, 2);
        ls1 += __shfl_xor_sync(0xffffffffu, ls1, 1);
        ls1 += __shfl_xor_sync(0xffffffffu, ls1, 2);
        l0 = l0 * corr0 + ls0;
        l1 = l1 * corr1 + ls1;
#pragma unroll
        for (int nt = 0; nt < 8; nt++) {
            oacc[nt][0] *= corr0; oacc[nt][1] *= corr0;
            oacc[nt][2] *= corr1; oacc[nt][3] *= corr1;
        }
        __syncwarp();
#pragma unroll
        for (int ks = 0; ks < 4; ks++) {
            unsigned p0 = Ps[wq0 + g][8 * ks + t];
            unsigned p1 = Ps[wq0 + g + 8][8 * ks + t];
            unsigned p2 = Ps[wq0 + g][8 * ks + t + 4];
            unsigned p3 = Ps[wq0 + g + 8][8 * ks + t + 4];
#pragma unroll
            for (int nt = 0; nt < 8; nt++) {
                unsigned b0 = Vs[buf][nt * 8 + g][8 * ks + t];
                unsigned b1 = Vs[buf][nt * 8 + g][8 * ks + t + 4];
                mma_f16(oacc[nt], p0, p1, p2, p3, b0, b1);
            }
        }
        __syncthreads();
    }
    float inv0 = 1.f / l0, inv1 = 1.f / l1;
    int r0 = qt * 64 + wq0 + g;
#pragma unroll
    for (int nt = 0; nt < 8; nt++) {
        int col = nt * 8 + 2 * t;
        *(unsigned*)(y + ((size_t)(b * SD + r0) * HQ + h) * HDH + col) =
            pack2(oacc[nt][0] * inv0, oacc[nt][1] * inv0);
        *(unsigned*)(y + ((size_t)(b * SD + r0 + 8) * HQ + h) * HDH + col) =
            pack2(oacc[nt][2] * inv1, oacc[nt][3] * inv1);
    }
}

__global__ void zero_cnt_k() {
    if (threadIdx.x < ED) g_cnt[threadIdx.x] = 0;
}
__global__ void scan_k() {
    if (threadIdx.x == 0) {
        int a = 0;
        for (int e = 0; e < ED; e++) { g_base[e] = a; a += g_cnt[e]; }
    }
}

// ---------------- MoE GEMM1 fp16 ----------------
__global__ __launch_bounds__(256) void moe1_tc(const __half* __restrict__ tin,
                                               const float* __restrict__ w1,
                                               const float* __restrict__ w3) {
    int e = blockIdx.z;
    int cnt = g_cnt[e];
    int bm = blockIdx.y;
    if (bm * 128 >= cnt) return;
    int bn = blockIdx.x;
    extern __shared__ unsigned dsm[];
    unsigned (*As)[128][SAH]  = (unsigned(*)[128][SAH])dsm;
    unsigned (*Bs1)[16][SBHM] = (unsigned(*)[16][SBHM])(dsm + 2 * 128 * SAH);
    unsigned (*Bs3)[16][SBHM] = (unsigned(*)[16][SBHM])(dsm + 2 * 128 * SAH + 2 * 16 * SBHM);
    int tid = threadIdx.x, lane = tid & 31, wid = tid >> 5;
    int wm = (wid >> 1) * 32, wn = (wid & 1) * 32;
    int g = lane >> 2, t = lane & 3;
    int arow = tid >> 2, achk = (tid & 3);
    int kb = tid >> 5, n0 = (tid & 31) * 2;
    int r0 = bm * 128 + arow, r1 = r0 + 64;
    int tk0 = g_tok[e * CAP + (r0 < cnt ? r0 : cnt - 1)];
    int tk1 = g_tok[e * CAP + (r1 < cnt ? r1 : cnt - 1)];
    const __half* Ag  = tin + (size_t)tk0 * HDIM + achk * 8;
    const __half* Ag2 = tin + (size_t)tk1 * HDIM + achk * 8;
    const float* B1 = w1 + (size_t)e * HDIM * IDIM + bn * 64 + n0;
    const float* B3 = w3 + (size_t)e * HDIM * IDIM + bn * 64 + n0;
    cp16(&As[0][arow][achk * 4], Ag);
    cp16(&As[0][arow + 64][achk * 4], Ag2);
    cp_commit();
    float2 b1_st[4], b3_st[4];
#pragma unroll
    for (int i = 0; i < 2; i++) {
        b1_st[i]     = *(const float2*)(B1 + (size_t)(2 * kb + i) * IDIM);
        b1_st[i + 2] = *(const float2*)(B1 + (size_t)(2 * kb + 16 + i) * IDIM);
        b3_st[i]     = *(const float2*)(B3 + (size_t)(2 * kb + i) * IDIM);
        b3_st[i + 2] = *(const float2*)(B3 + (size_t)(2 * kb + 16 + i) * IDIM);
    }
    float a1c[2][4][4] = {}, a3c[2][4][4] = {};
    const int nk = HDIM / 32;
    for (int kt = 0; kt < nk; kt++) {
        int p = kt & 1;
        cp_wait0();
        {
            uint2 u;
            u.x = pack2(b1_st[0].x, b1_st[1].x); u.y = pack2(b1_st[0].y, b1_st[1].y);
            *(uint2*)&Bs1[p][kb][n0] = u;
            u.x = pack2(b1_st[2].x, b1_st[3].x); u.y = pack2(b1_st[2].y, b1_st[3].y);
            *(uint2*)&Bs1[p][kb + 8][n0] = u;
            u.x = pack2(b3_st[0].x, b3_st[1].x); u.y = pack2(b3_st[0].y, b3_st[1].y);
            *(uint2*)&Bs3[p][kb][n0] = u;
            u.x = pack2(b3_st[2].x, b3_st[3].x); u.y = pack2(b3_st[2].y, b3_st[3].y);
            *(uint2*)&Bs3[p][kb + 8][n0] = u;
        }
        __syncthreads();
        if (kt + 1 < nk) {
            int ko = (kt + 1) * 32;
            cp16(&As[p ^ 1][arow][achk * 4], Ag + ko);
            cp16(&As[p ^ 1][arow + 64][achk * 4], Ag2 + ko);
#pragma unroll
            for (int i = 0; i < 2; i++) {
                b1_st[i]     = *(const float2*)(B1 + (size_t)(ko + 2 * kb + i) * IDIM);
                b1_st[i + 2] = *(const float2*)(B1 + (size_t)(ko + 2 * kb + 16 + i) * IDIM);
                b3_st[i]     = *(const float2*)(B3 + (size_t)(ko + 2 * kb + i) * IDIM);
                b3_st[i + 2] = *(const float2*)(B3 + (size_t)(ko + 2 * kb + 16 + i) * IDIM);
            }
        }
        cp_commit();
#pragma unroll
        for (int ks = 0; ks < 2; ks++) {
            int ko = ks * 8;
            unsigned af[2][4], bf1[4][2], bf3[4][2];
#pragma unroll
            for (int mi = 0; mi < 2; mi++) {
                int mb = wm + mi * 16;
                af[mi][0] = As[p][mb + g][ko + t];
                af[mi][1] = As[p][mb + g + 8][ko + t];
                af[mi][2] = As[p][mb + g][ko + t + 4];
                af[mi][3] = As[p][mb + g + 8][ko + t + 4];
            }
#pragma unroll
            for (int ni = 0; ni < 4; ni++) {
                int nb = wn + ni * 8;
                bf1[ni][0] = Bs1[p][ko + t][nb + g];
                bf1[ni][1] = Bs1[p][ko + t + 4][nb + g];
                bf3[ni][0] = Bs3[p][ko + t][nb + g];
                bf3[ni][1] = Bs3[p][ko + t + 4][nb + g];
            }
#pragma unroll
            for (int mi = 0; mi < 2; mi++)
#pragma unroll
                for (int ni = 0; ni < 4; ni++) {
                    mma_f16(a1c[mi][ni], af[mi][0], af[mi][1], af[mi][2], af[mi][3],
                            bf1[ni][0], bf1[ni][1]);
                    mma_f16(a3c[mi][ni], af[mi][0], af[mi][1], af[mi][2], af[mi][3],
                            bf3[ni][0], bf3[ni][1]);
                }
        }
    }
    int base = g_base[e];
#pragma unroll
    for (int mi = 0; mi < 2; mi++) {
#pragma unroll
        for (int ni = 0; ni < 4; ni++) {
            int row = bm * 128 + wm + mi * 16 + g;
            int col = bn * 64 + wn + ni * 8 + 2 * t;
#pragma unroll
            for (int half = 0; half < 2; half++) {
                int rr = row + half * 8;
                if (rr < cnt) {
                    float u0 = a1c[mi][ni][half * 2], h0 = a3c[mi][ni][half * 2];
                    float u1 = a1c[mi][ni][half * 2 + 1], h1 = a3c[mi][ni][half * 2 + 1];
                    float ox = (u0 / (1.f + __expf(-u0))) * h0;
                    float oy = (u1 / (1.f + __expf(-u1))) * h1;
                    *(unsigned*)(g_gbuf + (size_t)(base + rr) * IDIM + col) = pack2(ox, oy);
                }
            }
        }
    }
}

// ---------------- MoE GEMM2 fp16 ----------------
__global__ __launch_bounds__(256) void moe2_tc(const float* __restrict__ w2,
                                               float* __restrict__ out0) {
    int e = blockIdx.z;
    int cnt = g_cnt[e];
    int bm = blockIdx.y;
    if (bm * 128 >= cnt) return;
    int bn = blockIdx.x;
    extern __shared__ unsigned dsm[];
    unsigned (*As)[128][SAH] = (unsigned(*)[128][SAH])dsm;
    unsigned (*Bs)[16][SBH]  = (unsigned(*)[16][SBH])(dsm + 2 * 128 * SAH);
    int tid = threadIdx.x, lane = tid & 31, wid = tid >> 5;
    int wm = (wid >> 2) * 64, wn = (wid & 3) * 32;
    int g = lane >> 2, t = lane & 3;
    int arow = tid >> 2, achk = (tid & 3);
    int kb = tid >> 5, n0 = (tid & 31) * 4;
    int base = g_base[e];
    const __half* Ag  = g_gbuf + (size_t)(base + bm * 128 + arow) * IDIM + achk * 8;
    const __half* Ag2 = Ag + (size_t)64 * IDIM;
    const float* Bg = w2 + (size_t)e * IDIM * HDIM + bn * 128 + n0;
    cp16(&As[0][arow][achk * 4], Ag);
    cp16(&As[0][arow + 64][achk * 4], Ag2);
    cp_commit();
    float4 b_st[4];
#pragma unroll
    for (int i = 0; i < 2; i++) {
        b_st[i]     = *(const float4*)(Bg + (size_t)(2 * kb + i) * HDIM);
        b_st[i + 2] = *(const float4*)(Bg + (size_t)(2 * kb + 16 + i) * HDIM);
    }
    float acc[4][4][4] = {};
    const int nk = IDIM / 32;
    for (int kt = 0; kt < nk; kt++) {
        int p = kt & 1;
        cp_wait0();
        h16_stage_b(Bs[p], kb, n0, b_st);
        __syncthreads();
        if (kt + 1 < nk) {
            int ko = (kt + 1) * 32;
            cp16(&As[p ^ 1][arow][achk * 4], Ag + ko);
            cp16(&As[p ^ 1][arow + 64][achk * 4], Ag2 + ko);
            const float* Bn = Bg + (size_t)ko * HDIM;
#pragma unroll
            for (int i = 0; i < 2; i++) {
                b_st[i]     = *(const float4*)(Bn + (size_t)(2 * kb + i) * HDIM);
                b_st[i + 2] = *(const float4*)(Bn + (size_t)(2 * kb + 16 + i) * HDIM);
            }
        }
        cp_commit();
        h16_compute(wm, wn, g, t, As[p], Bs[p], acc);
    }
#pragma unroll
    for (int mi = 0; mi < 4; mi++) {
#pragma unroll
        for (int ni = 0; ni < 4; ni++) {
            int row = bm * 128 + wm + mi * 16 + g;
            int col = bn * 128 + wn + ni * 8 + 2 * t;
#pragma unroll
            for (int half = 0; half < 2; half++) {
                int rr = row + half * 8;
                if (rr < cnt) {
                    int token = g_tok[e * CAP + rr];
                    float wt = g_wt[e * CAP + rr];
                    float* op = out0 + (size_t)token * HDIM + col;
                    atomicAdd(op + 0, wt * acc[mi][ni][half * 2]);
                    atomicAdd(op + 1, wt * acc[mi][ni][half * 2 + 1]);
                }
            }
        }
    }
}

// ---------------- launch ----------------
extern "C" void kernel_launch(void* const* d_in, const int* in_sizes, int n_in,
                              void* d_out, int out_size) {
    const float* x    = (const float*)d_in[0];
    const float* freq = (const float*)d_in[1];
    const float* n1w  = (const float*)d_in[2];
    const float* n2w  = (const float*)d_in[3];
    const float* wq   = (const float*)d_in[4];
    const float* wk   = (const float*)d_in[5];
    const float* wv   = (const float*)d_in[6];
    const float* wo   = (const float*)d_in[7];
    const float* qnw  = (const float*)d_in[8];
    const float* knw  = (const float*)d_in[9];
    const float* gw   = (const float*)d_in[10];
    const float* w1   = (const float*)d_in[11];
    const float* w2   = (const float*)d_in[12];
    const float* w3   = (const float*)d_in[13];

    float* out0 = (float*)d_out;
    float* kout = out0 + (size_t)TD * HDIM;
    float* vout = kout + (size_t)TD * HKV * HDH;

    __half *hn, *yb, *tb, *qh, *kh, *vT;
    float *qb, *kp;
    cudaGetSymbolAddress((void**)&hn, g_hn);
    cudaGetSymbolAddress((void**)&qb, g_q);
    cudaGetSymbolAddress((void**)&kp, g_kproj);
    cudaGetSymbolAddress((void**)&qh, g_qh);
    cudaGetSymbolAddress((void**)&kh, g_kh);
    cudaGetSymbolAddress((void**)&vT, g_vT);
    cudaGetSymbolAddress((void**)&yb, g_y);
    cudaGetSymbolAddress((void**)&tb, g_t);

    cudaFuncSetAttribute(attn_h, cudaFuncAttributeMaxDynamicSharedMemorySize, ATT_SMEM);
    cudaFuncSetAttribute(gemm_tc, cudaFuncAttributeMaxDynamicSharedMemorySize, GEMM_SMEM);
    cudaFuncSetAttribute(qkv_tc, cudaFuncAttributeMaxDynamicSharedMemorySize, GEMM_SMEM);
    cudaFuncSetAttribute(moe1_tc, cudaFuncAttributeMaxDynamicSharedMemorySize, MOE1_SMEM);
    cudaFuncSetAttribute(moe2_tc, cudaFuncAttributeMaxDynamicSharedMemorySize, GEMM_SMEM);

    rmsnorm_k<<<TD, 256>>>(x, n1w, hn);
    qkv_tc<<<dim3(12, TD / 128), 256, GEMM_SMEM>>>(hn, wq, wk, wv, qb, kp, vout);
    qknorm_rope2_k<<<TD * (HQ + HKV), 64>>>(qb, kp, qnw, knw, freq, qh, kout, kh);
    vtrans_k<<<dim3(SD / 64, BD * HKV), 256>>>(vout, vT);
    attn_h<<<dim3(SD / 64, HQ, BD), 128, ATT_SMEM>>>(qh, kh, vT, yb);
    gemm_tc<<<dim3(HDIM / 128, TD / 128), 256, GEMM_SMEM>>>(yb, wo, out0, x, TD, HDIM, HDIM);
    zero_cnt_k<<<1, 32>>>();
    rmsgate_k<<<TD, 256>>>(out0, n2w, gw, tb);
    scan_k<<<1, 1>>>();
    moe1_tc<<<dim3(IDIM / 64, TD / 128, ED), 256, MOE1_SMEM>>>(tb, w1, w3);
    moe2_tc<<<dim3(HDIM / 128, TD / 128, ED), 256, GEMM_SMEM>>>(w2, out0);
}

// round 16
// speedup vs baseline: 1.1582x; 1.1582x over previous
#include <cuda_runtime.h>
#include <cuda_fp16.h>
#include <math.h>

#define BD 2
#define SD 1024
#define TD (BD*SD)
#define HDIM 1024
#define HQ 16
#define HKV 4
#define HDH 64
#define ED 8
#define IDIM 2048
#define CAP (2*TD)
#define EPSF 1e-6f

// fp16 GEMM smem strides (u32 units)
#define SAH 20
#define SBH 136
#define SBHM 72
#define GEMM_SMEM ((2*128*SAH + 2*16*SBH) * 4)
#define MOE1_SMEM ((2*128*SAH + 2*2*16*SBHM) * 4)

// ---------------- scratch ----------------
__device__ __half g_hn[TD*HDIM];
__device__ float  g_q[TD*HQ*HDH];
__device__ float  g_kproj[TD*HKV*HDH];
__device__ __half g_qh[TD*HQ*HDH];
__device__ __half g_kh[TD*HKV*HDH];
__device__ __half g_vT[(size_t)BD*HKV*HDH*SD];
__device__ __half g_y[TD*HQ*HDH];
__device__ __half g_t[TD*HDIM];
__device__ __half g_gbuf[(size_t)(CAP+128)*IDIM];
__device__ int    g_cnt[ED];
__device__ int    g_base[ED];
__device__ int    g_tok[ED*CAP];
__device__ float  g_wt[ED*CAP];

// ---------------- helpers ----------------
__device__ __forceinline__ void mma_f16(float* c,
                                        unsigned a0, unsigned a1, unsigned a2, unsigned a3,
                                        unsigned b0, unsigned b1) {
    asm volatile("mma.sync.aligned.m16n8k16.row.col.f32.f16.f16.f32 "
                 "{%0,%1,%2,%3}, {%4,%5,%6,%7}, {%8,%9}, {%0,%1,%2,%3};"
                 : "+f"(c[0]), "+f"(c[1]), "+f"(c[2]), "+f"(c[3])
                 : "r"(a0), "r"(a1), "r"(a2), "r"(a3), "r"(b0), "r"(b1));
}
__device__ __forceinline__ unsigned pack2(float lo, float hi) {
    __half2 h = __floats2half2_rn(lo, hi);
    return *(unsigned*)&h;
}
__device__ __forceinline__ void cp16(const void* sdst, const void* g) {
    unsigned a = (unsigned)__cvta_generic_to_shared(sdst);
    asm volatile("cp.async.cg.shared.global [%0], [%1], 16;" :: "r"(a), "l"(g));
}
__device__ __forceinline__ void cp_commit() { asm volatile("cp.async.commit_group;"); }
__device__ __forceinline__ void cp_wait0()  { asm volatile("cp.async.wait_group 0;"); }
__device__ __forceinline__ void cp_wait1()  { asm volatile("cp.async.wait_group 1;"); }

// ---------------- RMSNorm over H=1024, half output ----------------
__global__ __launch_bounds__(256) void rmsnorm_k(const float* __restrict__ x,
                                                 const float* __restrict__ w,
                                                 __half* __restrict__ out) {
    int row = blockIdx.x;
    int tid = threadIdx.x;
    const float* xr = x + (size_t)row * HDIM;
    float4 v = *(const float4*)(xr + tid * 4);
    float ss = v.x * v.x + v.y * v.y + v.z * v.z + v.w * v.w;
#pragma unroll
    for (int o = 16; o > 0; o >>= 1) ss += __shfl_xor_sync(0xffffffffu, ss, o);
    __shared__ float sred[8];
    if ((tid & 31) == 0) sred[tid >> 5] = ss;
    __syncthreads();
    float tot = ((sred[0] + sred[1]) + (sred[2] + sred[3])) +
                ((sred[4] + sred[5]) + (sred[6] + sred[7]));
    float mean = tot * (1.0f / HDIM) + EPSF;
    float r = rsqrtf(mean);
    r = r * (1.5f - 0.5f * mean * r * r);
    float4 w4 = *(const float4*)(w + tid * 4);
    __half* orow = out + (size_t)row * HDIM + tid * 4;
    *(unsigned*)(orow)     = pack2(v.x * r * w4.x, v.y * r * w4.y);
    *(unsigned*)(orow + 2) = pack2(v.z * r * w4.z, v.w * r * w4.w);
}

// ============ fp16 GEMM core ============
__device__ __forceinline__ void h16_compute(int wm, int wn, int g, int t,
                                            unsigned (*As)[SAH], unsigned (*Bs)[SBH],
                                            float acc[4][4][4]) {
#pragma unroll
    for (int ks = 0; ks < 2; ks++) {
        int ko = ks * 8;
        unsigned af[4][4], bf[4][2];
#pragma unroll
        for (int mi = 0; mi < 4; mi++) {
            int mb = wm + mi * 16;
            af[mi][0] = As[mb + g][ko + t];
            af[mi][1] = As[mb + g + 8][ko + t];
            af[mi][2] = As[mb + g][ko + t + 4];
            af[mi][3] = As[mb + g + 8][ko + t + 4];
        }
#pragma unroll
        for (int ni = 0; ni < 4; ni++) {
            int nb = wn + ni * 8;
            bf[ni][0] = Bs[ko + t][nb + g];
            bf[ni][1] = Bs[ko + t + 4][nb + g];
        }
#pragma unroll
        for (int mi = 0; mi < 4; mi++)
#pragma unroll
            for (int ni = 0; ni < 4; ni++)
                mma_f16(acc[mi][ni], af[mi][0], af[mi][1], af[mi][2], af[mi][3],
                        bf[ni][0], bf[ni][1]);
    }
}

__device__ __forceinline__ void h16_stage_b(unsigned (*Bs)[SBH], int kb, int n0,
                                            const float4 b_st[4]) {
    uint4 u0, u1;
    u0.x = pack2(b_st[0].x, b_st[1].x); u0.y = pack2(b_st[0].y, b_st[1].y);
    u0.z = pack2(b_st[0].z, b_st[1].z); u0.w = pack2(b_st[0].w, b_st[1].w);
    u1.x = pack2(b_st[2].x, b_st[3].x); u1.y = pack2(b_st[2].y, b_st[3].y);
    u1.z = pack2(b_st[2].z, b_st[3].z); u1.w = pack2(b_st[2].w, b_st[3].w);
    *(uint4*)&Bs[kb][n0]     = u0;
    *(uint4*)&Bs[kb + 8][n0] = u1;
}

// ---------------- generic GEMM (+resid) ----------------
__global__ __launch_bounds__(256) void gemm_tc(const __half* __restrict__ A,
                                               const float* __restrict__ Bm,
                                               float* __restrict__ C,
                                               const float* __restrict__ resid,
                                               int M, int N, int K) {
    extern __shared__ unsigned dsm[];
    unsigned (*As)[128][SAH] = (unsigned(*)[128][SAH])dsm;
    unsigned (*Bs)[16][SBH]  = (unsigned(*)[16][SBH])(dsm + 2 * 128 * SAH);
    int tid = threadIdx.x, lane = tid & 31, wid = tid >> 5;
    int wm = (wid >> 2) * 64, wn = (wid & 3) * 32;
    int g = lane >> 2, t = lane & 3;
    int arow = tid >> 2, achk = (tid & 3);
    int kb = tid >> 5, n0 = (tid & 31) * 4;
    int bm = blockIdx.y, bn = blockIdx.x;
    const __half* Ag = A + (size_t)(bm * 128 + arow) * K + achk * 8;
    const __half* Ag2 = Ag + (size_t)64 * K;
    const float* Bg = Bm + bn * 128 + n0;
    cp16(&As[0][arow][achk * 4], Ag);
    cp16(&As[0][arow + 64][achk * 4], Ag2);
    cp_commit();
    float4 b_st[4];
#pragma unroll
    for (int i = 0; i < 2; i++) {
        b_st[i]     = *(const float4*)(Bg + (size_t)(2 * kb + i) * N);
        b_st[i + 2] = *(const float4*)(Bg + (size_t)(2 * kb + 16 + i) * N);
    }
    float acc[4][4][4] = {};
    int nk = K / 32;
    for (int kt = 0; kt < nk; kt++) {
        int p = kt & 1;
        cp_wait0();
        h16_stage_b(Bs[p], kb, n0, b_st);
        __syncthreads();
        if (kt + 1 < nk) {
            int ko = (kt + 1) * 32;
            cp16(&As[p ^ 1][arow][achk * 4], Ag + ko);
            cp16(&As[p ^ 1][arow + 64][achk * 4], Ag2 + ko);
            const float* Bn = Bg + (size_t)ko * N;
#pragma unroll
            for (int i = 0; i < 2; i++) {
                b_st[i]     = *(const float4*)(Bn + (size_t)(2 * kb + i) * N);
                b_st[i + 2] = *(const float4*)(Bn + (size_t)(2 * kb + 16 + i) * N);
            }
        }
        cp_commit();
        h16_compute(wm, wn, g, t, As[p], Bs[p], acc);
    }
#pragma unroll
    for (int mi = 0; mi < 4; mi++) {
#pragma unroll
        for (int ni = 0; ni < 4; ni++) {
            int row0 = bm * 128 + wm + mi * 16 + g;
            int col = bn * 128 + wn + ni * 8 + 2 * t;
            size_t o0 = (size_t)row0 * N + col;
            size_t o1 = (size_t)(row0 + 8) * N + col;
            float2 v0 = make_float2(acc[mi][ni][0], acc[mi][ni][1]);
            float2 v1 = make_float2(acc[mi][ni][2], acc[mi][ni][3]);
            if (resid) {
                float2 r0 = *(const float2*)(resid + o0);
                float2 r1 = *(const float2*)(resid + o1);
                v0.x += r0.x; v0.y += r0.y; v1.x += r1.x; v1.y += r1.y;
            }
            *(float2*)(C + o0) = v0;
            *(float2*)(C + o1) = v1;
        }
    }
}

// ---------------- fused QKV projection ----------------
__global__ __launch_bounds__(256) void qkv_tc(const __half* __restrict__ hn,
                                              const float* __restrict__ wq,
                                              const float* __restrict__ wk,
                                              const float* __restrict__ wv,
                                              float* __restrict__ qb,
                                              float* __restrict__ kp,
                                              float* __restrict__ vo) {
    extern __shared__ unsigned dsm[];
    unsigned (*As)[128][SAH] = (unsigned(*)[128][SAH])dsm;
    unsigned (*Bs)[16][SBH]  = (unsigned(*)[16][SBH])(dsm + 2 * 128 * SAH);
    int tid = threadIdx.x, lane = tid & 31, wid = tid >> 5;
    int wm = (wid >> 2) * 64, wn = (wid & 3) * 32;
    int g = lane >> 2, t = lane & 3;
    int arow = tid >> 2, achk = (tid & 3);
    int kb = tid >> 5, n0 = (tid & 31) * 4;
    int bm = blockIdx.y, bn = blockIdx.x;
    const float* Bm; float* C; int N, coff;
    if (bn < 8)       { Bm = wq; C = qb; N = 1024; coff = bn * 128; }
    else if (bn < 10) { Bm = wk; C = kp; N = 256;  coff = (bn - 8) * 128; }
    else              { Bm = wv; C = vo; N = 256;  coff = (bn - 10) * 128; }
    const __half* Ag = hn + (size_t)(bm * 128 + arow) * HDIM + achk * 8;
    const __half* Ag2 = Ag + (size_t)64 * HDIM;
    const float* Bg = Bm + coff + n0;
    cp16(&As[0][arow][achk * 4], Ag);
    cp16(&As[0][arow + 64][achk * 4], Ag2);
    cp_commit();
    float4 b_st[4];
#pragma unroll
    for (int i = 0; i < 2; i++) {
        b_st[i]     = *(const float4*)(Bg + (size_t)(2 * kb + i) * N);
        b_st[i + 2] = *(const float4*)(Bg + (size_t)(2 * kb + 16 + i) * N);
    }
    float acc[4][4][4] = {};
    const int nk = HDIM / 32;
    for (int kt = 0; kt < nk; kt++) {
        int p = kt & 1;
        cp_wait0();
        h16_stage_b(Bs[p], kb, n0, b_st);
        __syncthreads();
        if (kt + 1 < nk) {
            int ko = (kt + 1) * 32;
            cp16(&As[p ^ 1][arow][achk * 4], Ag + ko);
            cp16(&As[p ^ 1][arow + 64][achk * 4], Ag2 + ko);
            const float* Bn = Bg + (size_t)ko * N;
#pragma unroll
            for (int i = 0; i < 2; i++) {
                b_st[i]     = *(const float4*)(Bn + (size_t)(2 * kb + i) * N);
                b_st[i + 2] = *(const float4*)(Bn + (size_t)(2 * kb + 16 + i) * N);
            }
        }
        cp_commit();
        h16_compute(wm, wn, g, t, As[p], Bs[p], acc);
    }
#pragma unroll
    for (int mi = 0; mi < 4; mi++) {
#pragma unroll
        for (int ni = 0; ni < 4; ni++) {
            int row0 = bm * 128 + wm + mi * 16 + g;
            int col = coff + wn + ni * 8 + 2 * t;
            *(float2*)(C + (size_t)row0 * N + col) =
                make_float2(acc[mi][ni][0], acc[mi][ni][1]);
            *(float2*)(C + (size_t)(row0 + 8) * N + col) =
                make_float2(acc[mi][ni][2], acc[mi][ni][3]);
        }
    }
}

// ------------- warp-per-row RMSNorm + RoPE: q -> half; k -> f32 + half ---------
// 8 rows per 256-thr block; lane j owns the (j, j+32) rotation pair. No smem.
__global__ __launch_bounds__(256) void qknorm_rope3_k(const float* __restrict__ qin,
                                                      const float* __restrict__ kin,
                                                      const float* __restrict__ qw,
                                                      const float* __restrict__ kw,
                                                      const float* __restrict__ freq,
                                                      __half* __restrict__ qh,
                                                      float* __restrict__ kout,
                                                      __half* __restrict__ kh) {
    int rid = blockIdx.x * 8 + (threadIdx.x >> 5);
    int lane = threadIdx.x & 31;
    const float* in; const float* w; int nH, idx;
    bool isq;
    if (rid < TD * HQ) { in = qin; w = qw; nH = HQ; idx = rid; isq = true; }
    else { idx = rid - TD * HQ; in = kin; w = kw; nH = HKV; isq = false; }
    int t = idx / nH;
    int s = t & (SD - 1);
    const float* ir = in + (size_t)idx * HDH;
    float v1 = ir[lane], v2 = ir[lane + 32];
    float ss = v1 * v1 + v2 * v2;
#pragma unroll
    for (int o = 16; o > 0; o >>= 1) ss += __shfl_xor_sync(0xffffffffu, ss, o);
    float mean = ss * (1.0f / HDH) + EPSF;
    float r = rsqrtf(mean);
    r = r * (1.5f - 0.5f * mean * r * r);
    float n1 = v1 * r * w[lane];
    float n2 = v2 * r * w[lane + 32];
    float f = freq[s * 32 + lane];
    float cf = cosf(f), sf = sinf(f);
    float o1 = n1 * cf - n2 * sf;
    float o2 = n1 * sf + n2 * cf;
    if (isq) {
        qh[(size_t)idx * HDH + lane] = __float2half(o1);
        qh[(size_t)idx * HDH + lane + 32] = __float2half(o2);
    } else {
        kout[(size_t)idx * HDH + lane] = o1;
        kout[(size_t)idx * HDH + lane + 32] = o2;
        kh[(size_t)idx * HDH + lane] = __float2half(o1);
        kh[(size_t)idx * HDH + lane + 32] = __float2half(o2);
    }
}

// ---------------- V transpose: 32-row tiles, grid 256 --------------------------
__global__ __launch_bounds__(256) void vtrans_k(const float* __restrict__ v,
                                                __half* __restrict__ vT) {
    __shared__ float sm[32][65];
    int st = blockIdx.x * 32;
    int bk = blockIdx.y;
    int b = bk >> 2, kvh = bk & 3;
    int tid = threadIdx.x;
    int s = tid >> 3, d0 = (tid & 7) * 8;
    const float* src = v + ((size_t)(b * SD + st + s) * HKV + kvh) * HDH + d0;
#pragma unroll
    for (int i = 0; i < 2; i++) {
        float4 x = *(const float4*)(src + i * 4);
        sm[s][d0 + i * 4]     = x.x; sm[s][d0 + i * 4 + 1] = x.y;
        sm[s][d0 + i * 4 + 2] = x.z; sm[s][d0 + i * 4 + 3] = x.w;
    }
    __syncthreads();
    int d = tid >> 2, s0 = (tid & 3) * 8;
    __half* dst = vT + ((size_t)bk * HDH + d) * SD + st + s0;
#pragma unroll
    for (int i = 0; i < 4; i++)
        *(unsigned*)(dst + i * 2) = pack2(sm[s0 + 2 * i][d], sm[s0 + 2 * i + 1][d]);
}

// ---------------- fp16 flash attention, 64-row Q tiles (R13), causal, GQA -------
#define AS_S 36
#define ATT_SMEM ((5*64*AS_S) * 4)

__global__ __launch_bounds__(128) void attn_h(const __half* __restrict__ q,
                                              const __half* __restrict__ k,
                                              const __half* __restrict__ vT,
                                              __half* __restrict__ y) {
    extern __shared__ unsigned smem[];
    unsigned (*Ks)[64][AS_S] = (unsigned(*)[64][AS_S])smem;
    unsigned (*Vs)[64][AS_S] = (unsigned(*)[64][AS_S])(smem + 2 * 64 * AS_S);
    unsigned (*Ps)[AS_S]     = (unsigned(*)[AS_S])(smem + 4 * 64 * AS_S);
    int qt = (SD / 64 - 1) - blockIdx.x;
    int h = blockIdx.y, b = blockIdx.z;
    int tid = threadIdx.x, lane = tid & 31, wid = tid >> 5;
    int g = lane >> 2, t = lane & 3;
    int kvh = h >> 2;
    int wq0 = wid * 16;
    const float scale = 0.125f;
    const __half* kbase = k + (size_t)kvh * HDH + (size_t)b * SD * HKV * HDH;
    const __half* vbase = vT + ((size_t)(b * HKV + kvh)) * HDH * SD;

#pragma unroll
    for (int i = 0; i < 4; i++) {
        int idx = tid + 128 * i;
        int r = idx >> 3, c = idx & 7;
        cp16(&Ps[r][c * 4], q + ((size_t)(b * SD + qt * 64 + r) * HQ + h) * HDH + c * 8);
    }
    cp_commit();
#pragma unroll
    for (int i = 0; i < 4; i++) {
        int idx = tid + 128 * i;
        int r = idx >> 3, c = idx & 7;
        cp16(&Ks[0][r][c * 4], kbase + (size_t)r * HKV * HDH + c * 8);
        cp16(&Vs[0][r][c * 4], vbase + (size_t)r * SD + c * 8);
    }
    cp_commit();
    cp_wait0();
    __syncthreads();
    unsigned qf[4][4];
#pragma unroll
    for (int ks = 0; ks < 4; ks++) {
        qf[ks][0] = Ps[wq0 + g][8 * ks + t];
        qf[ks][1] = Ps[wq0 + g + 8][8 * ks + t];
        qf[ks][2] = Ps[wq0 + g][8 * ks + t + 4];
        qf[ks][3] = Ps[wq0 + g + 8][8 * ks + t + 4];
    }
    __syncthreads();
    float m0 = -1e30f, m1 = -1e30f, l0 = 0.f, l1 = 0.f;
    float oacc[8][4] = {};

    for (int kt = 0; kt <= qt; kt++) {
        int buf = kt & 1;
        if (kt < qt) {
#pragma unroll
            for (int i = 0; i < 4; i++) {
                int idx = tid + 128 * i;
                int r = idx >> 3, c = idx & 7;
                cp16(&Ks[buf ^ 1][r][c * 4],
                     kbase + (size_t)((kt + 1) * 64 + r) * HKV * HDH + c * 8);
                cp16(&Vs[buf ^ 1][r][c * 4],
                     vbase + (size_t)r * SD + (kt + 1) * 64 + c * 8);
            }
            cp_commit();
            cp_wait1();
        } else {
            cp_wait0();
        }
        __syncthreads();
        float sacc[8][4] = {};
#pragma unroll
        for (int ks = 0; ks < 4; ks++) {
#pragma unroll
            for (int nt = 0; nt < 8; nt++) {
                unsigned b0 = Ks[buf][nt * 8 + g][8 * ks + t];
                unsigned b1 = Ks[buf][nt * 8 + g][8 * ks + t + 4];
                mma_f16(sacc[nt], qf[ks][0], qf[ks][1], qf[ks][2], qf[ks][3], b0, b1);
            }
        }
        float mx0 = -1e30f, mx1 = -1e30f;
        if (kt == qt) {
            int r0 = wq0 + g, r1 = r0 + 8;
#pragma unroll
            for (int nt = 0; nt < 8; nt++) {
                int c0 = nt * 8 + 2 * t, c1 = c0 + 1;
                sacc[nt][0] = (c0 <= r0) ? sacc[nt][0] * scale : -1e30f;
                sacc[nt][1] = (c1 <= r0) ? sacc[nt][1] * scale : -1e30f;
                sacc[nt][2] = (c0 <= r1) ? sacc[nt][2] * scale : -1e30f;
                sacc[nt][3] = (c1 <= r1) ? sacc[nt][3] * scale : -1e30f;
                mx0 = fmaxf(mx0, fmaxf(sacc[nt][0], sacc[nt][1]));
                mx1 = fmaxf(mx1, fmaxf(sacc[nt][2], sacc[nt][3]));
            }
        } else {
#pragma unroll
            for (int nt = 0; nt < 8; nt++) {
                sacc[nt][0] *= scale; sacc[nt][1] *= scale;
                sacc[nt][2] *= scale; sacc[nt][3] *= scale;
                mx0 = fmaxf(mx0, fmaxf(sacc[nt][0], sacc[nt][1]));
                mx1 = fmaxf(mx1, fmaxf(sacc[nt][2], sacc[nt][3]));
            }
        }
        mx0 = fmaxf(mx0, __shfl_xor_sync(0xffffffffu, mx0, 1));
        mx0 = fmaxf(mx0, __shfl_xor_sync(0xffffffffu, mx0, 2));
        mx1 = fmaxf(mx1, __shfl_xor_sync(0xffffffffu, mx1, 1));
        mx1 = fmaxf(mx1, __shfl_xor_sync(0xffffffffu, mx1, 2));
        float nm0 = fmaxf(m0, mx0), nm1 = fmaxf(m1, mx1);
        float corr0 = __expf(m0 - nm0), corr1 = __expf(m1 - nm1);
        m0 = nm0; m1 = nm1;
        float ls0 = 0.f, ls1 = 0.f;
#pragma unroll
        for (int nt = 0; nt < 8; nt++) {
            float p0 = __expf(sacc[nt][0] - nm0);
            float p1 = __expf(sacc[nt][1] - nm0);
            float p2 = __expf(sacc[nt][2] - nm1);
            float p3 = __expf(sacc[nt][3] - nm1);
            ls0 += p0 + p1; ls1 += p2 + p3;
            Ps[wq0 + g][nt * 4 + t]     = pack2(p0, p1);
            Ps[wq0 + g + 8][nt * 4 + t] = pack2(p2, p3);
        }
        ls0 += __shfl_xor_sync(0xffffffffu, ls0, 1);
        ls0 += __shfl_xor_sync(0xffffffffu, ls0, 2);
        ls1 += __shfl_xor_sync(0xffffffffu, ls1, 1);
        ls1 += __shfl_xor_sync(0xffffffffu, ls1, 2);
        l0 = l0 * corr0 + ls0;
        l1 = l1 * corr1 + ls1;
#pragma unroll
        for (int nt = 0; nt < 8; nt++) {
            oacc[nt][0] *= corr0; oacc[nt][1] *= corr0;
            oacc[nt][2] *= corr1; oacc[nt][3] *= corr1;
        }
        __syncwarp();
#pragma unroll
        for (int ks = 0; ks < 4; ks++) {
            unsigned p0 = Ps[wq0 + g][8 * ks + t];
            unsigned p1 = Ps[wq0 + g + 8][8 * ks + t];
            unsigned p2 = Ps[wq0 + g][8 * ks + t + 4];
            unsigned p3 = Ps[wq0 + g + 8][8 * ks + t + 4];
#pragma unroll
            for (int nt = 0; nt < 8; nt++) {
                unsigned b0 = Vs[buf][nt * 8 + g][8 * ks + t];
                unsigned b1 = Vs[buf][nt * 8 + g][8 * ks + t + 4];
                mma_f16(oacc[nt], p0, p1, p2, p3, b0, b1);
            }
        }
        __syncthreads();
    }
    float inv0 = 1.f / l0, inv1 = 1.f / l1;
    int r0 = qt * 64 + wq0 + g;
#pragma unroll
    for (int nt = 0; nt < 8; nt++) {
        int col = nt * 8 + 2 * t;
        *(unsigned*)(y + ((size_t)(b * SD + r0) * HQ + h) * HDH + col) =
            pack2(oacc[nt][0] * inv0, oacc[nt][1] * inv0);
        *(unsigned*)(y + ((size_t)(b * SD + r0 + 8) * HQ + h) * HDH + col) =
            pack2(oacc[nt][2] * inv1, oacc[nt][3] * inv1);
    }
}

// ---------------- gate (half input; R13 version) ----------------
__global__ __launch_bounds__(256) void gate_k(const __half* __restrict__ t,
                                              const float* __restrict__ gw) {
    int tok = blockIdx.x;
    const __half* tr = t + (size_t)tok * HDIM;
    float acc[ED];
#pragma unroll
    for (int e = 0; e < ED; e++) acc[e] = 0.f;
    for (int h = threadIdx.x; h < HDIM; h += 256) {
        float tv = __half2float(tr[h]);
        const float* g = gw + (size_t)h * ED;
#pragma unroll
        for (int e = 0; e < ED; e++) acc[e] += tv * g[e];
    }
#pragma unroll
    for (int e = 0; e < ED; e++)
#pragma unroll
        for (int o = 16; o > 0; o >>= 1) acc[e] += __shfl_xor_sync(0xffffffffu, acc[e], o);
    __shared__ float sr[8][ED];
    int wid = threadIdx.x >> 5, lane = threadIdx.x & 31;
    if (lane == 0) {
#pragma unroll
        for (int e = 0; e < ED; e++) sr[wid][e] = acc[e];
    }
    __syncthreads();
    if (threadIdx.x == 0) {
        float lg[ED];
#pragma unroll
        for (int e = 0; e < ED; e++) {
            float s = 0.f;
            for (int w = 0; w < 8; w++) s += sr[w][e];
            lg[e] = s;
        }
        int i1 = 0; float v1 = lg[0];
        for (int e = 1; e < ED; e++) if (lg[e] > v1) { v1 = lg[e]; i1 = e; }
        int i2 = -1; float v2 = -3.4e38f;
        for (int e = 0; e < ED; e++) if (e != i1 && lg[e] > v2) { v2 = lg[e]; i2 = e; }
        float bexp = __expf(v2 - v1);
        float wA = 1.f / (1.f + bexp);
        float wB = bexp / (1.f + bexp);
        int p1 = atomicAdd(&g_cnt[i1], 1);
        g_tok[i1 * CAP + p1] = tok; g_wt[i1 * CAP + p1] = wA;
        int p2 = atomicAdd(&g_cnt[i2], 1);
        g_tok[i2 * CAP + p2] = tok; g_wt[i2 * CAP + p2] = wB;
    }
}

__global__ void zero_cnt_k() {
    if (threadIdx.x < ED) g_cnt[threadIdx.x] = 0;
}
__global__ void scan_k() {
    if (threadIdx.x == 0) {
        int a = 0;
        for (int e = 0; e < ED; e++) { g_base[e] = a; a += g_cnt[e]; }
    }
}

// ---------------- MoE GEMM1 fp16 ----------------
__global__ __launch_bounds__(256) void moe1_tc(const __half* __restrict__ tin,
                                               const float* __restrict__ w1,
                                               const float* __restrict__ w3) {
    int e = blockIdx.z;
    int cnt = g_cnt[e];
    int bm = blockIdx.y;
    if (bm * 128 >= cnt) return;
    int bn = blockIdx.x;
    extern __shared__ unsigned dsm[];
    unsigned (*As)[128][SAH]  = (unsigned(*)[128][SAH])dsm;
    unsigned (*Bs1)[16][SBHM] = (unsigned(*)[16][SBHM])(dsm + 2 * 128 * SAH);
    unsigned (*Bs3)[16][SBHM] = (unsigned(*)[16][SBHM])(dsm + 2 * 128 * SAH + 2 * 16 * SBHM);
    int tid = threadIdx.x, lane = tid & 31, wid = tid >> 5;
    int wm = (wid >> 1) * 32, wn = (wid & 1) * 32;
    int g = lane >> 2, t = lane & 3;
    int arow = tid >> 2, achk = (tid & 3);
    int kb = tid >> 5, n0 = (tid & 31) * 2;
    int r0 = bm * 128 + arow, r1 = r0 + 64;
    int tk0 = g_tok[e * CAP + (r0 < cnt ? r0 : cnt - 1)];
    int tk1 = g_tok[e * CAP + (r1 < cnt ? r1 : cnt - 1)];
    const __half* Ag  = tin + (size_t)tk0 * HDIM + achk * 8;
    const __half* Ag2 = tin + (size_t)tk1 * HDIM + achk * 8;
    const float* B1 = w1 + (size_t)e * HDIM * IDIM + bn * 64 + n0;
    const float* B3 = w3 + (size_t)e * HDIM * IDIM + bn * 64 + n0;
    cp16(&As[0][arow][achk * 4], Ag);
    cp16(&As[0][arow + 64][achk * 4], Ag2);
    cp_commit();
    float2 b1_st[4], b3_st[4];
#pragma unroll
    for (int i = 0; i < 2; i++) {
        b1_st[i]     = *(const float2*)(B1 + (size_t)(2 * kb + i) * IDIM);
        b1_st[i + 2] = *(const float2*)(B1 + (size_t)(2 * kb + 16 + i) * IDIM);
        b3_st[i]     = *(const float2*)(B3 + (size_t)(2 * kb + i) * IDIM);
        b3_st[i + 2] = *(const float2*)(B3 + (size_t)(2 * kb + 16 + i) * IDIM);
    }
    float a1c[2][4][4] = {}, a3c[2][4][4] = {};
    const int nk = HDIM / 32;
    for (int kt = 0; kt < nk; kt++) {
        int p = kt & 1;
        cp_wait0();
        {
            uint2 u;
            u.x = pack2(b1_st[0].x, b1_st[1].x); u.y = pack2(b1_st[0].y, b1_st[1].y);
            *(uint2*)&Bs1[p][kb][n0] = u;
            u.x = pack2(b1_st[2].x, b1_st[3].x); u.y = pack2(b1_st[2].y, b1_st[3].y);
            *(uint2*)&Bs1[p][kb + 8][n0] = u;
            u.x = pack2(b3_st[0].x, b3_st[1].x); u.y = pack2(b3_st[0].y, b3_st[1].y);
            *(uint2*)&Bs3[p][kb][n0] = u;
            u.x = pack2(b3_st[2].x, b3_st[3].x); u.y = pack2(b3_st[2].y, b3_st[3].y);
            *(uint2*)&Bs3[p][kb + 8][n0] = u;
        }
        __syncthreads();
        if (kt + 1 < nk) {
            int ko = (kt + 1) * 32;
            cp16(&As[p ^ 1][arow][achk * 4], Ag + ko);
            cp16(&As[p ^ 1][arow + 64][achk * 4], Ag2 + ko);
#pragma unroll
            for (int i = 0; i < 2; i++) {
                b1_st[i]     = *(const float2*)(B1 + (size_t)(ko + 2 * kb + i) * IDIM);
                b1_st[i + 2] = *(const float2*)(B1 + (size_t)(ko + 2 * kb + 16 + i) * IDIM);
                b3_st[i]     = *(const float2*)(B3 + (size_t)(ko + 2 * kb + i) * IDIM);
                b3_st[i + 2] = *(const float2*)(B3 + (size_t)(ko + 2 * kb + 16 + i) * IDIM);
            }
        }
        cp_commit();
#pragma unroll
        for (int ks = 0; ks < 2; ks++) {
            int ko = ks * 8;
            unsigned af[2][4], bf1[4][2], bf3[4][2];
#pragma unroll
            for (int mi = 0; mi < 2; mi++) {
                int mb = wm + mi * 16;
                af[mi][0] = As[p][mb + g][ko + t];
                af[mi][1] = As[p][mb + g + 8][ko + t];
                af[mi][2] = As[p][mb + g][ko + t + 4];
                af[mi][3] = As[p][mb + g + 8][ko + t + 4];
            }
#pragma unroll
            for (int ni = 0; ni < 4; ni++) {
                int nb = wn + ni * 8;
                bf1[ni][0] = Bs1[p][ko + t][nb + g];
                bf1[ni][1] = Bs1[p][ko + t + 4][nb + g];
                bf3[ni][0] = Bs3[p][ko + t][nb + g];
                bf3[ni][1] = Bs3[p][ko + t + 4][nb + g];
            }
#pragma unroll
            for (int mi = 0; mi < 2; mi++)
#pragma unroll
                for (int ni = 0; ni < 4; ni++) {
                    mma_f16(a1c[mi][ni], af[mi][0], af[mi][1], af[mi][2], af[mi][3],
                            bf1[ni][0], bf1[ni][1]);
                    mma_f16(a3c[mi][ni], af[mi][0], af[mi][1], af[mi][2], af[mi][3],
                            bf3[ni][0], bf3[ni][1]);
                }
        }
    }
    int base = g_base[e];
#pragma unroll
    for (int mi = 0; mi < 2; mi++) {
#pragma unroll
        for (int ni = 0; ni < 4; ni++) {
            int row = bm * 128 + wm + mi * 16 + g;
            int col = bn * 64 + wn + ni * 8 + 2 * t;
#pragma unroll
            for (int half = 0; half < 2; half++) {
                int rr = row + half * 8;
                if (rr < cnt) {
                    float u0 = a1c[mi][ni][half * 2], h0 = a3c[mi][ni][half * 2];
                    float u1 = a1c[mi][ni][half * 2 + 1], h1 = a3c[mi][ni][half * 2 + 1];
                    float ox = (u0 / (1.f + __expf(-u0))) * h0;
                    float oy = (u1 / (1.f + __expf(-u1))) * h1;
                    *(unsigned*)(g_gbuf + (size_t)(base + rr) * IDIM + col) = pack2(ox, oy);
                }
            }
        }
    }
}

// ---------------- MoE GEMM2 fp16 ----------------
__global__ __launch_bounds__(256) void moe2_tc(const float* __restrict__ w2,
                                               float* __restrict__ out0) {
    int e = blockIdx.z;
    int cnt = g_cnt[e];
    int bm = blockIdx.y;
    if (bm * 128 >= cnt) return;
    int bn = blockIdx.x;
    extern __shared__ unsigned dsm[];
    unsigned (*As)[128][SAH] = (unsigned(*)[128][SAH])dsm;
    unsigned (*Bs)[16][SBH]  = (unsigned(*)[16][SBH])(dsm + 2 * 128 * SAH);
    int tid = threadIdx.x, lane = tid & 31, wid = tid >> 5;
    int wm = (wid >> 2) * 64, wn = (wid & 3) * 32;
    int g = lane >> 2, t = lane & 3;
    int arow = tid >> 2, achk = (tid & 3);
    int kb = tid >> 5, n0 = (tid & 31) * 4;
    int base = g_base[e];
    const __half* Ag  = g_gbuf + (size_t)(base + bm * 128 + arow) * IDIM + achk * 8;
    const __half* Ag2 = Ag + (size_t)64 * IDIM;
    const float* Bg = w2 + (size_t)e * IDIM * HDIM + bn * 128 + n0;
    cp16(&As[0][arow][achk * 4], Ag);
    cp16(&As[0][arow + 64][achk * 4], Ag2);
    cp_commit();
    float4 b_st[4];
#pragma unroll
    for (int i = 0; i < 2; i++) {
        b_st[i]     = *(const float4*)(Bg + (size_t)(2 * kb + i) * HDIM);
        b_st[i + 2] = *(const float4*)(Bg + (size_t)(2 * kb + 16 + i) * HDIM);
    }
    float acc[4][4][4] = {};
    const int nk = IDIM / 32;
    for (int kt = 0; kt < nk; kt++) {
        int p = kt & 1;
        cp_wait0();
        h16_stage_b(Bs[p], kb, n0, b_st);
        __syncthreads();
        if (kt + 1 < nk) {
            int ko = (kt + 1) * 32;
            cp16(&As[p ^ 1][arow][achk * 4], Ag + ko);
            cp16(&As[p ^ 1][arow + 64][achk * 4], Ag2 + ko);
            const float* Bn = Bg + (size_t)ko * HDIM;
#pragma unroll
            for (int i = 0; i < 2; i++) {
                b_st[i]     = *(const float4*)(Bn + (size_t)(2 * kb + i) * HDIM);
                b_st[i + 2] = *(const float4*)(Bn + (size_t)(2 * kb + 16 + i) * HDIM);
            }
        }
        cp_commit();
        h16_compute(wm, wn, g, t, As[p], Bs[p], acc);
    }
#pragma unroll
    for (int mi = 0; mi < 4; mi++) {
#pragma unroll
        for (int ni = 0; ni < 4; ni++) {
            int row = bm * 128 + wm + mi * 16 + g;
            int col = bn * 128 + wn + ni * 8 + 2 * t;
#pragma unroll
            for (int half = 0; half < 2; half++) {
                int rr = row + half * 8;
                if (rr < cnt) {
                    int token = g_tok[e * CAP + rr];
                    float wt = g_wt[e * CAP + rr];
                    float* op = out0 + (size_t)token * HDIM + col;
                    atomicAdd(op + 0, wt * acc[mi][ni][half * 2]);
                    atomicAdd(op + 1, wt * acc[mi][ni][half * 2 + 1]);
                }
            }
        }
    }
}

// ---------------- launch ----------------
extern "C" void kernel_launch(void* const* d_in, const int* in_sizes, int n_in,
                              void* d_out, int out_size) {
    const float* x    = (const float*)d_in[0];
    const float* freq = (const float*)d_in[1];
    const float* n1w  = (const float*)d_in[2];
    const float* n2w  = (const float*)d_in[3];
    const float* wq   = (const float*)d_in[4];
    const float* wk   = (const float*)d_in[5];
    const float* wv   = (const float*)d_in[6];
    const float* wo   = (const float*)d_in[7];
    const float* qnw  = (const float*)d_in[8];
    const float* knw  = (const float*)d_in[9];
    const float* gw   = (const float*)d_in[10];
    const float* w1   = (const float*)d_in[11];
    const float* w2   = (const float*)d_in[12];
    const float* w3   = (const float*)d_in[13];

    float* out0 = (float*)d_out;
    float* kout = out0 + (size_t)TD * HDIM;
    float* vout = kout + (size_t)TD * HKV * HDH;

    __half *hn, *yb, *tb, *qh, *kh, *vT;
    float *qb, *kp;
    cudaGetSymbolAddress((void**)&hn, g_hn);
    cudaGetSymbolAddress((void**)&qb, g_q);
    cudaGetSymbolAddress((void**)&kp, g_kproj);
    cudaGetSymbolAddress((void**)&qh, g_qh);
    cudaGetSymbolAddress((void**)&kh, g_kh);
    cudaGetSymbolAddress((void**)&vT, g_vT);
    cudaGetSymbolAddress((void**)&yb, g_y);
    cudaGetSymbolAddress((void**)&tb, g_t);

    cudaFuncSetAttribute(attn_h, cudaFuncAttributeMaxDynamicSharedMemorySize, ATT_SMEM);
    cudaFuncSetAttribute(gemm_tc, cudaFuncAttributeMaxDynamicSharedMemorySize, GEMM_SMEM);
    cudaFuncSetAttribute(qkv_tc, cudaFuncAttributeMaxDynamicSharedMemorySize, GEMM_SMEM);
    cudaFuncSetAttribute(moe1_tc, cudaFuncAttributeMaxDynamicSharedMemorySize, MOE1_SMEM);
    cudaFuncSetAttribute(moe2_tc, cudaFuncAttributeMaxDynamicSharedMemorySize, GEMM_SMEM);

    rmsnorm_k<<<TD, 256>>>(x, n1w, hn);
    qkv_tc<<<dim3(12, TD / 128), 256, GEMM_SMEM>>>(hn, wq, wk, wv, qb, kp, vout);
    qknorm_rope3_k<<<TD * (HQ + HKV) / 8, 256>>>(qb, kp, qnw, knw, freq, qh, kout, kh);
    vtrans_k<<<dim3(SD / 32, BD * HKV), 256>>>(vout, vT);
    attn_h<<<dim3(SD / 64, HQ, BD), 128, ATT_SMEM>>>(qh, kh, vT, yb);
    gemm_tc<<<dim3(HDIM / 128, TD / 128), 256, GEMM_SMEM>>>(yb, wo, out0, x, TD, HDIM, HDIM);
    rmsnorm_k<<<TD, 256>>>(out0, n2w, tb);
    zero_cnt_k<<<1, 32>>>();
    gate_k<<<TD, 256>>>(tb, gw);
    scan_k<<<1, 1>>>();
    moe1_tc<<<dim3(IDIM / 64, TD / 128, ED), 256, MOE1_SMEM>>>(tb, w1, w3);
    moe2_tc<<<dim3(HDIM / 128, TD / 128, ED), 256, GEMM_SMEM>>>(w2, out0);
}

// round 17
// speedup vs baseline: 1.1716x; 1.0116x over previous
#include <cuda_runtime.h>
#include <cuda_fp16.h>
#include <math.h>

#define BD 2
#define SD 1024
#define TD (BD*SD)
#define HDIM 1024
#define HQ 16
#define HKV 4
#define HDH 64
#define ED 8
#define IDIM 2048
#define CAP (2*TD)
#define EPSF 1e-6f

// fp16 GEMM smem strides (u32 units)
#define SAH 20
#define SBH 136
#define SBHM 72
#define GEMM_SMEM ((2*128*SAH + 2*16*SBH) * 4)
#define MOE1_SMEM ((2*128*SAH + 2*2*16*SBHM) * 4)

// ---------------- scratch ----------------
__device__ __half g_hn[TD*HDIM];
__device__ float  g_q[TD*HQ*HDH];
__device__ float  g_kproj[TD*HKV*HDH];
__device__ __half g_qh[TD*HQ*HDH];
__device__ __half g_kh[TD*HKV*HDH];
__device__ __half g_vT[(size_t)BD*HKV*HDH*SD];
__device__ __half g_y[TD*HQ*HDH];
__device__ __half g_t[TD*HDIM];
__device__ __half g_gbuf[(size_t)(CAP+128)*IDIM];
__device__ int    g_cnt[ED];
__device__ int    g_tok[ED*CAP];
__device__ float  g_wt[ED*CAP];

// ---------------- helpers ----------------
__device__ __forceinline__ void mma_f16(float* c,
                                        unsigned a0, unsigned a1, unsigned a2, unsigned a3,
                                        unsigned b0, unsigned b1) {
    asm volatile("mma.sync.aligned.m16n8k16.row.col.f32.f16.f16.f32 "
                 "{%0,%1,%2,%3}, {%4,%5,%6,%7}, {%8,%9}, {%0,%1,%2,%3};"
                 : "+f"(c[0]), "+f"(c[1]), "+f"(c[2]), "+f"(c[3])
                 : "r"(a0), "r"(a1), "r"(a2), "r"(a3), "r"(b0), "r"(b1));
}
__device__ __forceinline__ unsigned pack2(float lo, float hi) {
    __half2 h = __floats2half2_rn(lo, hi);
    return *(unsigned*)&h;
}
__device__ __forceinline__ void cp16(const void* sdst, const void* g) {
    unsigned a = (unsigned)__cvta_generic_to_shared(sdst);
    asm volatile("cp.async.cg.shared.global [%0], [%1], 16;" :: "r"(a), "l"(g));
}
__device__ __forceinline__ void cp_commit() { asm volatile("cp.async.commit_group;"); }
__device__ __forceinline__ void cp_wait0()  { asm volatile("cp.async.wait_group 0;"); }
__device__ __forceinline__ void cp_wait1()  { asm volatile("cp.async.wait_group 1;"); }

// ---------------- RMSNorm over H=1024, half output (+counter zeroing) -----------
__global__ __launch_bounds__(256) void rmsnorm_k(const float* __restrict__ x,
                                                 const float* __restrict__ w,
                                                 __half* __restrict__ out) {
    int row = blockIdx.x;
    int tid = threadIdx.x;
    if (row == 0 && tid < ED) g_cnt[tid] = 0;   // runs before gate_k fills; idempotent
    const float* xr = x + (size_t)row * HDIM;
    float4 v = *(const float4*)(xr + tid * 4);
    float ss = v.x * v.x + v.y * v.y + v.z * v.z + v.w * v.w;
#pragma unroll
    for (int o = 16; o > 0; o >>= 1) ss += __shfl_xor_sync(0xffffffffu, ss, o);
    __shared__ float sred[8];
    if ((tid & 31) == 0) sred[tid >> 5] = ss;
    __syncthreads();
    float tot = ((sred[0] + sred[1]) + (sred[2] + sred[3])) +
                ((sred[4] + sred[5]) + (sred[6] + sred[7]));
    float mean = tot * (1.0f / HDIM) + EPSF;
    float r = rsqrtf(mean);
    r = r * (1.5f - 0.5f * mean * r * r);
    float4 w4 = *(const float4*)(w + tid * 4);
    __half* orow = out + (size_t)row * HDIM + tid * 4;
    *(unsigned*)(orow)     = pack2(v.x * r * w4.x, v.y * r * w4.y);
    *(unsigned*)(orow + 2) = pack2(v.z * r * w4.z, v.w * r * w4.w);
}

// ============ fp16 GEMM core ============
__device__ __forceinline__ void h16_compute(int wm, int wn, int g, int t,
                                            unsigned (*As)[SAH], unsigned (*Bs)[SBH],
                                            float acc[4][4][4]) {
#pragma unroll
    for (int ks = 0; ks < 2; ks++) {
        int ko = ks * 8;
        unsigned af[4][4], bf[4][2];
#pragma unroll
        for (int mi = 0; mi < 4; mi++) {
            int mb = wm + mi * 16;
            af[mi][0] = As[mb + g][ko + t];
            af[mi][1] = As[mb + g + 8][ko + t];
            af[mi][2] = As[mb + g][ko + t + 4];
            af[mi][3] = As[mb + g + 8][ko + t + 4];
        }
#pragma unroll
        for (int ni = 0; ni < 4; ni++) {
            int nb = wn + ni * 8;
            bf[ni][0] = Bs[ko + t][nb + g];
            bf[ni][1] = Bs[ko + t + 4][nb + g];
        }
#pragma unroll
        for (int mi = 0; mi < 4; mi++)
#pragma unroll
            for (int ni = 0; ni < 4; ni++)
                mma_f16(acc[mi][ni], af[mi][0], af[mi][1], af[mi][2], af[mi][3],
                        bf[ni][0], bf[ni][1]);
    }
}

__device__ __forceinline__ void h16_stage_b(unsigned (*Bs)[SBH], int kb, int n0,
                                            const float4 b_st[4]) {
    uint4 u0, u1;
    u0.x = pack2(b_st[0].x, b_st[1].x); u0.y = pack2(b_st[0].y, b_st[1].y);
    u0.z = pack2(b_st[0].z, b_st[1].z); u0.w = pack2(b_st[0].w, b_st[1].w);
    u1.x = pack2(b_st[2].x, b_st[3].x); u1.y = pack2(b_st[2].y, b_st[3].y);
    u1.z = pack2(b_st[2].z, b_st[3].z); u1.w = pack2(b_st[2].w, b_st[3].w);
    *(uint4*)&Bs[kb][n0]     = u0;
    *(uint4*)&Bs[kb + 8][n0] = u1;
}

// ---------------- generic GEMM (+resid) ----------------
__global__ __launch_bounds__(256) void gemm_tc(const __half* __restrict__ A,
                                               const float* __restrict__ Bm,
                                               float* __restrict__ C,
                                               const float* __restrict__ resid,
                                               int M, int N, int K) {
    extern __shared__ unsigned dsm[];
    unsigned (*As)[128][SAH] = (unsigned(*)[128][SAH])dsm;
    unsigned (*Bs)[16][SBH]  = (unsigned(*)[16][SBH])(dsm + 2 * 128 * SAH);
    int tid = threadIdx.x, lane = tid & 31, wid = tid >> 5;
    int wm = (wid >> 2) * 64, wn = (wid & 3) * 32;
    int g = lane >> 2, t = lane & 3;
    int arow = tid >> 2, achk = (tid & 3);
    int kb = tid >> 5, n0 = (tid & 31) * 4;
    int bm = blockIdx.y, bn = blockIdx.x;
    const __half* Ag = A + (size_t)(bm * 128 + arow) * K + achk * 8;
    const __half* Ag2 = Ag + (size_t)64 * K;
    const float* Bg = Bm + bn * 128 + n0;
    cp16(&As[0][arow][achk * 4], Ag);
    cp16(&As[0][arow + 64][achk * 4], Ag2);
    cp_commit();
    float4 b_st[4];
#pragma unroll
    for (int i = 0; i < 2; i++) {
        b_st[i]     = *(const float4*)(Bg + (size_t)(2 * kb + i) * N);
        b_st[i + 2] = *(const float4*)(Bg + (size_t)(2 * kb + 16 + i) * N);
    }
    float acc[4][4][4] = {};
    int nk = K / 32;
    for (int kt = 0; kt < nk; kt++) {
        int p = kt & 1;
        cp_wait0();
        h16_stage_b(Bs[p], kb, n0, b_st);
        __syncthreads();
        if (kt + 1 < nk) {
            int ko = (kt + 1) * 32;
            cp16(&As[p ^ 1][arow][achk * 4], Ag + ko);
            cp16(&As[p ^ 1][arow + 64][achk * 4], Ag2 + ko);
            const float* Bn = Bg + (size_t)ko * N;
#pragma unroll
            for (int i = 0; i < 2; i++) {
                b_st[i]     = *(const float4*)(Bn + (size_t)(2 * kb + i) * N);
                b_st[i + 2] = *(const float4*)(Bn + (size_t)(2 * kb + 16 + i) * N);
            }
        }
        cp_commit();
        h16_compute(wm, wn, g, t, As[p], Bs[p], acc);
    }
#pragma unroll
    for (int mi = 0; mi < 4; mi++) {
#pragma unroll
        for (int ni = 0; ni < 4; ni++) {
            int row0 = bm * 128 + wm + mi * 16 + g;
            int col = bn * 128 + wn + ni * 8 + 2 * t;
            size_t o0 = (size_t)row0 * N + col;
            size_t o1 = (size_t)(row0 + 8) * N + col;
            float2 v0 = make_float2(acc[mi][ni][0], acc[mi][ni][1]);
            float2 v1 = make_float2(acc[mi][ni][2], acc[mi][ni][3]);
            if (resid) {
                float2 r0 = *(const float2*)(resid + o0);
                float2 r1 = *(const float2*)(resid + o1);
                v0.x += r0.x; v0.y += r0.y; v1.x += r1.x; v1.y += r1.y;
            }
            *(float2*)(C + o0) = v0;
            *(float2*)(C + o1) = v1;
        }
    }
}

// ---------------- fused QKV projection ----------------
__global__ __launch_bounds__(256) void qkv_tc(const __half* __restrict__ hn,
                                              const float* __restrict__ wq,
                                              const float* __restrict__ wk,
                                              const float* __restrict__ wv,
                                              float* __restrict__ qb,
                                              float* __restrict__ kp,
                                              float* __restrict__ vo) {
    extern __shared__ unsigned dsm[];
    unsigned (*As)[128][SAH] = (unsigned(*)[128][SAH])dsm;
    unsigned (*Bs)[16][SBH]  = (unsigned(*)[16][SBH])(dsm + 2 * 128 * SAH);
    int tid = threadIdx.x, lane = tid & 31, wid = tid >> 5;
    int wm = (wid >> 2) * 64, wn = (wid & 3) * 32;
    int g = lane >> 2, t = lane & 3;
    int arow = tid >> 2, achk = (tid & 3);
    int kb = tid >> 5, n0 = (tid & 31) * 4;
    int bm = blockIdx.y, bn = blockIdx.x;
    const float* Bm; float* C; int N, coff;
    if (bn < 8)       { Bm = wq; C = qb; N = 1024; coff = bn * 128; }
    else if (bn < 10) { Bm = wk; C = kp; N = 256;  coff = (bn - 8) * 128; }
    else              { Bm = wv; C = vo; N = 256;  coff = (bn - 10) * 128; }
    const __half* Ag = hn + (size_t)(bm * 128 + arow) * HDIM + achk * 8;
    const __half* Ag2 = Ag + (size_t)64 * HDIM;
    const float* Bg = Bm + coff + n0;
    cp16(&As[0][arow][achk * 4], Ag);
    cp16(&As[0][arow + 64][achk * 4], Ag2);
    cp_commit();
    float4 b_st[4];
#pragma unroll
    for (int i = 0; i < 2; i++) {
        b_st[i]     = *(const float4*)(Bg + (size_t)(2 * kb + i) * N);
        b_st[i + 2] = *(const float4*)(Bg + (size_t)(2 * kb + 16 + i) * N);
    }
    float acc[4][4][4] = {};
    const int nk = HDIM / 32;
    for (int kt = 0; kt < nk; kt++) {
        int p = kt & 1;
        cp_wait0();
        h16_stage_b(Bs[p], kb, n0, b_st);
        __syncthreads();
        if (kt + 1 < nk) {
            int ko = (kt + 1) * 32;
            cp16(&As[p ^ 1][arow][achk * 4], Ag + ko);
            cp16(&As[p ^ 1][arow + 64][achk * 4], Ag2 + ko);
            const float* Bn = Bg + (size_t)ko * N;
#pragma unroll
            for (int i = 0; i < 2; i++) {
                b_st[i]     = *(const float4*)(Bn + (size_t)(2 * kb + i) * N);
                b_st[i + 2] = *(const float4*)(Bn + (size_t)(2 * kb + 16 + i) * N);
            }
        }
        cp_commit();
        h16_compute(wm, wn, g, t, As[p], Bs[p], acc);
    }
#pragma unroll
    for (int mi = 0; mi < 4; mi++) {
#pragma unroll
        for (int ni = 0; ni < 4; ni++) {
            int row0 = bm * 128 + wm + mi * 16 + g;
            int col = coff + wn + ni * 8 + 2 * t;
            *(float2*)(C + (size_t)row0 * N + col) =
                make_float2(acc[mi][ni][0], acc[mi][ni][1]);
            *(float2*)(C + (size_t)(row0 + 8) * N + col) =
                make_float2(acc[mi][ni][2], acc[mi][ni][3]);
        }
    }
}

// ------------- warp-per-row RMSNorm + RoPE: q -> half; k -> f32 + half ---------
__global__ __launch_bounds__(256) void qknorm_rope3_k(const float* __restrict__ qin,
                                                      const float* __restrict__ kin,
                                                      const float* __restrict__ qw,
                                                      const float* __restrict__ kw,
                                                      const float* __restrict__ freq,
                                                      __half* __restrict__ qh,
                                                      float* __restrict__ kout,
                                                      __half* __restrict__ kh) {
    int rid = blockIdx.x * 8 + (threadIdx.x >> 5);
    int lane = threadIdx.x & 31;
    const float* in; const float* w; int nH, idx;
    bool isq;
    if (rid < TD * HQ) { in = qin; w = qw; nH = HQ; idx = rid; isq = true; }
    else { idx = rid - TD * HQ; in = kin; w = kw; nH = HKV; isq = false; }
    int t = idx / nH;
    int s = t & (SD - 1);
    const float* ir = in + (size_t)idx * HDH;
    float v1 = ir[lane], v2 = ir[lane + 32];
    float ss = v1 * v1 + v2 * v2;
#pragma unroll
    for (int o = 16; o > 0; o >>= 1) ss += __shfl_xor_sync(0xffffffffu, ss, o);
    float mean = ss * (1.0f / HDH) + EPSF;
    float r = rsqrtf(mean);
    r = r * (1.5f - 0.5f * mean * r * r);
    float n1 = v1 * r * w[lane];
    float n2 = v2 * r * w[lane + 32];
    float f = freq[s * 32 + lane];
    float cf = cosf(f), sf = sinf(f);
    float o1 = n1 * cf - n2 * sf;
    float o2 = n1 * sf + n2 * cf;
    if (isq) {
        qh[(size_t)idx * HDH + lane] = __float2half(o1);
        qh[(size_t)idx * HDH + lane + 32] = __float2half(o2);
    } else {
        kout[(size_t)idx * HDH + lane] = o1;
        kout[(size_t)idx * HDH + lane + 32] = o2;
        kh[(size_t)idx * HDH + lane] = __float2half(o1);
        kh[(size_t)idx * HDH + lane + 32] = __float2half(o2);
    }
}

// ---------------- V transpose: 32-row tiles, grid 256 --------------------------
__global__ __launch_bounds__(256) void vtrans_k(const float* __restrict__ v,
                                                __half* __restrict__ vT) {
    __shared__ float sm[32][65];
    int st = blockIdx.x * 32;
    int bk = blockIdx.y;
    int b = bk >> 2, kvh = bk & 3;
    int tid = threadIdx.x;
    int s = tid >> 3, d0 = (tid & 7) * 8;
    const float* src = v + ((size_t)(b * SD + st + s) * HKV + kvh) * HDH + d0;
#pragma unroll
    for (int i = 0; i < 2; i++) {
        float4 x = *(const float4*)(src + i * 4);
        sm[s][d0 + i * 4]     = x.x; sm[s][d0 + i * 4 + 1] = x.y;
        sm[s][d0 + i * 4 + 2] = x.z; sm[s][d0 + i * 4 + 3] = x.w;
    }
    __syncthreads();
    int d = tid >> 2, s0 = (tid & 3) * 8;
    __half* dst = vT + ((size_t)bk * HDH + d) * SD + st + s0;
#pragma unroll
    for (int i = 0; i < 4; i++)
        *(unsigned*)(dst + i * 2) = pack2(sm[s0 + 2 * i][d], sm[s0 + 2 * i + 1][d]);
}

// ---------------- fp16 flash attention, 64-row Q tiles, causal, GQA ------------
#define AS_S 36
#define ATT_SMEM ((5*64*AS_S) * 4)

__global__ __launch_bounds__(128) void attn_h(const __half* __restrict__ q,
                                              const __half* __restrict__ k,
                                              const __half* __restrict__ vT,
                                              __half* __restrict__ y) {
    extern __shared__ unsigned smem[];
    unsigned (*Ks)[64][AS_S] = (unsigned(*)[64][AS_S])smem;
    unsigned (*Vs)[64][AS_S] = (unsigned(*)[64][AS_S])(smem + 2 * 64 * AS_S);
    unsigned (*Ps)[AS_S]     = (unsigned(*)[AS_S])(smem + 4 * 64 * AS_S);
    int qt = (SD / 64 - 1) - blockIdx.x;
    int h = blockIdx.y, b = blockIdx.z;
    int tid = threadIdx.x, lane = tid & 31, wid = tid >> 5;
    int g = lane >> 2, t = lane & 3;
    int kvh = h >> 2;
    int wq0 = wid * 16;
    const float scale = 0.125f;
    const __half* kbase = k + (size_t)kvh * HDH + (size_t)b * SD * HKV * HDH;
    const __half* vbase = vT + ((size_t)(b * HKV + kvh)) * HDH * SD;

#pragma unroll
    for (int i = 0; i < 4; i++) {
        int idx = tid + 128 * i;
        int r = idx >> 3, c = idx & 7;
        cp16(&Ps[r][c * 4], q + ((size_t)(b * SD + qt * 64 + r) * HQ + h) * HDH + c * 8);
    }
    cp_commit();
#pragma unroll
    for (int i = 0; i < 4; i++) {
        int idx = tid + 128 * i;
        int r = idx >> 3, c = idx & 7;
        cp16(&Ks[0][r][c * 4], kbase + (size_t)r * HKV * HDH + c * 8);
        cp16(&Vs[0][r][c * 4], vbase + (size_t)r * SD + c * 8);
    }
    cp_commit();
    cp_wait0();
    __syncthreads();
    unsigned qf[4][4];
#pragma unroll
    for (int ks = 0; ks < 4; ks++) {
        qf[ks][0] = Ps[wq0 + g][8 * ks + t];
        qf[ks][1] = Ps[wq0 + g + 8][8 * ks + t];
        qf[ks][2] = Ps[wq0 + g][8 * ks + t + 4];
        qf[ks][3] = Ps[wq0 + g + 8][8 * ks + t + 4];
    }
    __syncthreads();
    float m0 = -1e30f, m1 = -1e30f, l0 = 0.f, l1 = 0.f;
    float oacc[8][4] = {};

    for (int kt = 0; kt <= qt; kt++) {
        int buf = kt & 1;
        if (kt < qt) {
#pragma unroll
            for (int i = 0; i < 4; i++) {
                int idx = tid + 128 * i;
                int r = idx >> 3, c = idx & 7;
                cp16(&Ks[buf ^ 1][r][c * 4],
                     kbase + (size_t)((kt + 1) * 64 + r) * HKV * HDH + c * 8);
                cp16(&Vs[buf ^ 1][r][c * 4],
                     vbase + (size_t)r * SD + (kt + 1) * 64 + c * 8);
            }
            cp_commit();
            cp_wait1();
        } else {
            cp_wait0();
        }
        __syncthreads();
        float sacc[8][4] = {};
#pragma unroll
        for (int ks = 0; ks < 4; ks++) {
#pragma unroll
            for (int nt = 0; nt < 8; nt++) {
                unsigned b0 = Ks[buf][nt * 8 + g][8 * ks + t];
                unsigned b1 = Ks[buf][nt * 8 + g][8 * ks + t + 4];
                mma_f16(sacc[nt], qf[ks][0], qf[ks][1], qf[ks][2], qf[ks][3], b0, b1);
            }
        }
        float mx0 = -1e30f, mx1 = -1e30f;
        if (kt == qt) {
            int r0 = wq0 + g, r1 = r0 + 8;
#pragma unroll
            for (int nt = 0; nt < 8; nt++) {
                int c0 = nt * 8 + 2 * t, c1 = c0 + 1;
                sacc[nt][0] = (c0 <= r0) ? sacc[nt][0] * scale : -1e30f;
                sacc[nt][1] = (c1 <= r0) ? sacc[nt][1] * scale : -1e30f;
                sacc[nt][2] = (c0 <= r1) ? sacc[nt][2] * scale : -1e30f;
                sacc[nt][3] = (c1 <= r1) ? sacc[nt][3] * scale : -1e30f;
                mx0 = fmaxf(mx0, fmaxf(sacc[nt][0], sacc[nt][1]));
                mx1 = fmaxf(mx1, fmaxf(sacc[nt][2], sacc[nt][3]));
            }
        } else {
#pragma unroll
            for (int nt = 0; nt < 8; nt++) {
                sacc[nt][0] *= scale; sacc[nt][1] *= scale;
                sacc[nt][2] *= scale; sacc[nt][3] *= scale;
                mx0 = fmaxf(mx0, fmaxf(sacc[nt][0], sacc[nt][1]));
                mx1 = fmaxf(mx1, fmaxf(sacc[nt][2], sacc[nt][3]));
            }
        }
        mx0 = fmaxf(mx0, __shfl_xor_sync(0xffffffffu, mx0, 1));
        mx0 = fmaxf(mx0, __shfl_xor_sync(0xffffffffu, mx0, 2));
        mx1 = fmaxf(mx1, __shfl_xor_sync(0xffffffffu, mx1, 1));
        mx1 = fmaxf(mx1, __shfl_xor_sync(0xffffffffu, mx1, 2));
        float nm0 = fmaxf(m0, mx0), nm1 = fmaxf(m1, mx1);
        float corr0 = __expf(m0 - nm0), corr1 = __expf(m1 - nm1);
        m0 = nm0; m1 = nm1;
        float ls0 = 0.f, ls1 = 0.f;
#pragma unroll
        for (int nt = 0; nt < 8; nt++) {
            float p0 = __expf(sacc[nt][0] - nm0);
            float p1 = __expf(sacc[nt][1] - nm0);
            float p2 = __expf(sacc[nt][2] - nm1);
            float p3 = __expf(sacc[nt][3] - nm1);
            ls0 += p0 + p1; ls1 += p2 + p3;
            Ps[wq0 + g][nt * 4 + t]     = pack2(p0, p1);
            Ps[wq0 + g + 8][nt * 4 + t] = pack2(p2, p3);
        }
        ls0 += __shfl_xor_sync(0xffffffffu, ls0, 1);
        ls0 += __shfl_xor_sync(0xffffffffu, ls0, 2);
        ls1 += __shfl_xor_sync(0xffffffffu, ls1, 1);
        ls1 += __shfl_xor_sync(0xffffffffu, ls1, 2);
        l0 = l0 * corr0 + ls0;
        l1 = l1 * corr1 + ls1;
#pragma unroll
        for (int nt = 0; nt < 8; nt++) {
            oacc[nt][0] *= corr0; oacc[nt][1] *= corr0;
            oacc[nt][2] *= corr1; oacc[nt][3] *= corr1;
        }
        __syncwarp();
#pragma unroll
        for (int ks = 0; ks < 4; ks++) {
            unsigned p0 = Ps[wq0 + g][8 * ks + t];
            unsigned p1 = Ps[wq0 + g + 8][8 * ks + t];
            unsigned p2 = Ps[wq0 + g][8 * ks + t + 4];
            unsigned p3 = Ps[wq0 + g + 8][8 * ks + t + 4];
#pragma unroll
            for (int nt = 0; nt < 8; nt++) {
                unsigned b0 = Vs[buf][nt * 8 + g][8 * ks + t];
                unsigned b1 = Vs[buf][nt * 8 + g][8 * ks + t + 4];
                mma_f16(oacc[nt], p0, p1, p2, p3, b0, b1);
            }
        }
        __syncthreads();
    }
    float inv0 = 1.f / l0, inv1 = 1.f / l1;
    int r0 = qt * 64 + wq0 + g;
#pragma unroll
    for (int nt = 0; nt < 8; nt++) {
        int col = nt * 8 + 2 * t;
        *(unsigned*)(y + ((size_t)(b * SD + r0) * HQ + h) * HDH + col) =
            pack2(oacc[nt][0] * inv0, oacc[nt][1] * inv0);
        *(unsigned*)(y + ((size_t)(b * SD + r0 + 8) * HQ + h) * HDH + col) =
            pack2(oacc[nt][2] * inv1, oacc[nt][3] * inv1);
    }
}

// ---------------- gate (half input) ----------------
__global__ __launch_bounds__(256) void gate_k(const __half* __restrict__ t,
                                              const float* __restrict__ gw) {
    int tok = blockIdx.x;
    const __half* tr = t + (size_t)tok * HDIM;
    float acc[ED];
#pragma unroll
    for (int e = 0; e < ED; e++) acc[e] = 0.f;
    for (int h = threadIdx.x; h < HDIM; h += 256) {
        float tv = __half2float(tr[h]);
        const float* g = gw + (size_t)h * ED;
#pragma unroll
        for (int e = 0; e < ED; e++) acc[e] += tv * g[e];
    }
#pragma unroll
    for (int e = 0; e < ED; e++)
#pragma unroll
        for (int o = 16; o > 0; o >>= 1) acc[e] += __shfl_xor_sync(0xffffffffu, acc[e], o);
    __shared__ float sr[8][ED];
    int wid = threadIdx.x >> 5, lane = threadIdx.x & 31;
    if (lane == 0) {
#pragma unroll
        for (int e = 0; e < ED; e++) sr[wid][e] = acc[e];
    }
    __syncthreads();
    if (threadIdx.x == 0) {
        float lg[ED];
#pragma unroll
        for (int e = 0; e < ED; e++) {
            float s = 0.f;
            for (int w = 0; w < 8; w++) s += sr[w][e];
            lg[e] = s;
        }
        int i1 = 0; float v1 = lg[0];
        for (int e = 1; e < ED; e++) if (lg[e] > v1) { v1 = lg[e]; i1 = e; }
        int i2 = -1; float v2 = -3.4e38f;
        for (int e = 0; e < ED; e++) if (e != i1 && lg[e] > v2) { v2 = lg[e]; i2 = e; }
        float bexp = __expf(v2 - v1);
        float wA = 1.f / (1.f + bexp);
        float wB = bexp / (1.f + bexp);
        int p1 = atomicAdd(&g_cnt[i1], 1);
        g_tok[i1 * CAP + p1] = tok; g_wt[i1 * CAP + p1] = wA;
        int p2 = atomicAdd(&g_cnt[i2], 1);
        g_tok[i2 * CAP + p2] = tok; g_wt[i2 * CAP + p2] = wB;
    }
}

// ---------------- MoE GEMM1 fp16 (inline prefix base) ----------------
__global__ __launch_bounds__(256) void moe1_tc(const __half* __restrict__ tin,
                                               const float* __restrict__ w1,
                                               const float* __restrict__ w3) {
    int e = blockIdx.z;
    int cnt = g_cnt[e];
    int bm = blockIdx.y;
    if (bm * 128 >= cnt) return;
    int bn = blockIdx.x;
    int base = 0;
#pragma unroll
    for (int i = 0; i < ED; i++) base += (i < e) ? g_cnt[i] : 0;
    extern __shared__ unsigned dsm[];
    unsigned (*As)[128][SAH]  = (unsigned(*)[128][SAH])dsm;
    unsigned (*Bs1)[16][SBHM] = (unsigned(*)[16][SBHM])(dsm + 2 * 128 * SAH);
    unsigned (*Bs3)[16][SBHM] = (unsigned(*)[16][SBHM])(dsm + 2 * 128 * SAH + 2 * 16 * SBHM);
    int tid = threadIdx.x, lane = tid & 31, wid = tid >> 5;
    int wm = (wid >> 1) * 32, wn = (wid & 1) * 32;
    int g = lane >> 2, t = lane & 3;
    int arow = tid >> 2, achk = (tid & 3);
    int kb = tid >> 5, n0 = (tid & 31) * 2;
    int r0 = bm * 128 + arow, r1 = r0 + 64;
    int tk0 = g_tok[e * CAP + (r0 < cnt ? r0 : cnt - 1)];
    int tk1 = g_tok[e * CAP + (r1 < cnt ? r1 : cnt - 1)];
    const __half* Ag  = tin + (size_t)tk0 * HDIM + achk * 8;
    const __half* Ag2 = tin + (size_t)tk1 * HDIM + achk * 8;
    const float* B1 = w1 + (size_t)e * HDIM * IDIM + bn * 64 + n0;
    const float* B3 = w3 + (size_t)e * HDIM * IDIM + bn * 64 + n0;
    cp16(&As[0][arow][achk * 4], Ag);
    cp16(&As[0][arow + 64][achk * 4], Ag2);
    cp_commit();
    float2 b1_st[4], b3_st[4];
#pragma unroll
    for (int i = 0; i < 2; i++) {
        b1_st[i]     = *(const float2*)(B1 + (size_t)(2 * kb + i) * IDIM);
        b1_st[i + 2] = *(const float2*)(B1 + (size_t)(2 * kb + 16 + i) * IDIM);
        b3_st[i]     = *(const float2*)(B3 + (size_t)(2 * kb + i) * IDIM);
        b3_st[i + 2] = *(const float2*)(B3 + (size_t)(2 * kb + 16 + i) * IDIM);
    }
    float a1c[2][4][4] = {}, a3c[2][4][4] = {};
    const int nk = HDIM / 32;
    for (int kt = 0; kt < nk; kt++) {
        int p = kt & 1;
        cp_wait0();
        {
            uint2 u;
            u.x = pack2(b1_st[0].x, b1_st[1].x); u.y = pack2(b1_st[0].y, b1_st[1].y);
            *(uint2*)&Bs1[p][kb][n0] = u;
            u.x = pack2(b1_st[2].x, b1_st[3].x); u.y = pack2(b1_st[2].y, b1_st[3].y);
            *(uint2*)&Bs1[p][kb + 8][n0] = u;
            u.x = pack2(b3_st[0].x, b3_st[1].x); u.y = pack2(b3_st[0].y, b3_st[1].y);
            *(uint2*)&Bs3[p][kb][n0] = u;
            u.x = pack2(b3_st[2].x, b3_st[3].x); u.y = pack2(b3_st[2].y, b3_st[3].y);
            *(uint2*)&Bs3[p][kb + 8][n0] = u;
        }
        __syncthreads();
        if (kt + 1 < nk) {
            int ko = (kt + 1) * 32;
            cp16(&As[p ^ 1][arow][achk * 4], Ag + ko);
            cp16(&As[p ^ 1][arow + 64][achk * 4], Ag2 + ko);
#pragma unroll
            for (int i = 0; i < 2; i++) {
                b1_st[i]     = *(const float2*)(B1 + (size_t)(ko + 2 * kb + i) * IDIM);
                b1_st[i + 2] = *(const float2*)(B1 + (size_t)(ko + 2 * kb + 16 + i) * IDIM);
                b3_st[i]     = *(const float2*)(B3 + (size_t)(ko + 2 * kb + i) * IDIM);
                b3_st[i + 2] = *(const float2*)(B3 + (size_t)(ko + 2 * kb + 16 + i) * IDIM);
            }
        }
        cp_commit();
#pragma unroll
        for (int ks = 0; ks < 2; ks++) {
            int ko = ks * 8;
            unsigned af[2][4], bf1[4][2], bf3[4][2];
#pragma unroll
            for (int mi = 0; mi < 2; mi++) {
                int mb = wm + mi * 16;
                af[mi][0] = As[p][mb + g][ko + t];
                af[mi][1] = As[p][mb + g + 8][ko + t];
                af[mi][2] = As[p][mb + g][ko + t + 4];
                af[mi][3] = As[p][mb + g + 8][ko + t + 4];
            }
#pragma unroll
            for (int ni = 0; ni < 4; ni++) {
                int nb = wn + ni * 8;
                bf1[ni][0] = Bs1[p][ko + t][nb + g];
                bf1[ni][1] = Bs1[p][ko + t + 4][nb + g];
                bf3[ni][0] = Bs3[p][ko + t][nb + g];
                bf3[ni][1] = Bs3[p][ko + t + 4][nb + g];
            }
#pragma unroll
            for (int mi = 0; mi < 2; mi++)
#pragma unroll
                for (int ni = 0; ni < 4; ni++) {
                    mma_f16(a1c[mi][ni], af[mi][0], af[mi][1], af[mi][2], af[mi][3],
                            bf1[ni][0], bf1[ni][1]);
                    mma_f16(a3c[mi][ni], af[mi][0], af[mi][1], af[mi][2], af[mi][3],
                            bf3[ni][0], bf3[ni][1]);
                }
        }
    }
#pragma unroll
    for (int mi = 0; mi < 2; mi++) {
#pragma unroll
        for (int ni = 0; ni < 4; ni++) {
            int row = bm * 128 + wm + mi * 16 + g;
            int col = bn * 64 + wn + ni * 8 + 2 * t;
#pragma unroll
            for (int half = 0; half < 2; half++) {
                int rr = row + half * 8;
                if (rr < cnt) {
                    float u0 = a1c[mi][ni][half * 2], h0 = a3c[mi][ni][half * 2];
                    float u1 = a1c[mi][ni][half * 2 + 1], h1 = a3c[mi][ni][half * 2 + 1];
                    float ox = (u0 / (1.f + __expf(-u0))) * h0;
                    float oy = (u1 / (1.f + __expf(-u1))) * h1;
                    *(unsigned*)(g_gbuf + (size_t)(base + rr) * IDIM + col) = pack2(ox, oy);
                }
            }
        }
    }
}

// ---------------- MoE GEMM2 fp16 (inline prefix base) ----------------
__global__ __launch_bounds__(256) void moe2_tc(const float* __restrict__ w2,
                                               float* __restrict__ out0) {
    int e = blockIdx.z;
    int cnt = g_cnt[e];
    int bm = blockIdx.y;
    if (bm * 128 >= cnt) return;
    int bn = blockIdx.x;
    int base = 0;
#pragma unroll
    for (int i = 0; i < ED; i++) base += (i < e) ? g_cnt[i] : 0;
    extern __shared__ unsigned dsm[];
    unsigned (*As)[128][SAH] = (unsigned(*)[128][SAH])dsm;
    unsigned (*Bs)[16][SBH]  = (unsigned(*)[16][SBH])(dsm + 2 * 128 * SAH);
    int tid = threadIdx.x, lane = tid & 31, wid = tid >> 5;
    int wm = (wid >> 2) * 64, wn = (wid & 3) * 32;
    int g = lane >> 2, t = lane & 3;
    int arow = tid >> 2, achk = (tid & 3);
    int kb = tid >> 5, n0 = (tid & 31) * 4;
    const __half* Ag  = g_gbuf + (size_t)(base + bm * 128 + arow) * IDIM + achk * 8;
    const __half* Ag2 = Ag + (size_t)64 * IDIM;
    const float* Bg = w2 + (size_t)e * IDIM * HDIM + bn * 128 + n0;
    cp16(&As[0][arow][achk * 4], Ag);
    cp16(&As[0][arow + 64][achk * 4], Ag2);
    cp_commit();
    float4 b_st[4];
#pragma unroll
    for (int i = 0; i < 2; i++) {
        b_st[i]     = *(const float4*)(Bg + (size_t)(2 * kb + i) * HDIM);
        b_st[i + 2] = *(const float4*)(Bg + (size_t)(2 * kb + 16 + i) * HDIM);
    }
    float acc[4][4][4] = {};
    const int nk = IDIM / 32;
    for (int kt = 0; kt < nk; kt++) {
        int p = kt & 1;
        cp_wait0();
        h16_stage_b(Bs[p], kb, n0, b_st);
        __syncthreads();
        if (kt + 1 < nk) {
            int ko = (kt + 1) * 32;
            cp16(&As[p ^ 1][arow][achk * 4], Ag + ko);
            cp16(&As[p ^ 1][arow + 64][achk * 4], Ag2 + ko);
            const float* Bn = Bg + (size_t)ko * HDIM;
#pragma unroll
            for (int i = 0; i < 2; i++) {
                b_st[i]     = *(const float4*)(Bn + (size_t)(2 * kb + i) * HDIM);
                b_st[i + 2] = *(const float4*)(Bn + (size_t)(2 * kb + 16 + i) * HDIM);
            }
        }
        cp_commit();
        h16_compute(wm, wn, g, t, As[p], Bs[p], acc);
    }
#pragma unroll
    for (int mi = 0; mi < 4; mi++) {
#pragma unroll
        for (int ni = 0; ni < 4; ni++) {
            int row = bm * 128 + wm + mi * 16 + g;
            int col = bn * 128 + wn + ni * 8 + 2 * t;
#pragma unroll
            for (int half = 0; half < 2; half++) {
                int rr = row + half * 8;
                if (rr < cnt) {
                    int token = g_tok[e * CAP + rr];
                    float wt = g_wt[e * CAP + rr];
                    float* op = out0 + (size_t)token * HDIM + col;
                    atomicAdd(op + 0, wt * acc[mi][ni][half * 2]);
                    atomicAdd(op + 1, wt * acc[mi][ni][half * 2 + 1]);
                }
            }
        }
    }
}

// ---------------- launch ----------------
extern "C" void kernel_launch(void* const* d_in, const int* in_sizes, int n_in,
                              void* d_out, int out_size) {
    const float* x    = (const float*)d_in[0];
    const float* freq = (const float*)d_in[1];
    const float* n1w  = (const float*)d_in[2];
    const float* n2w  = (const float*)d_in[3];
    const float* wq   = (const float*)d_in[4];
    const float* wk   = (const float*)d_in[5];
    const float* wv   = (const float*)d_in[6];
    const float* wo   = (const float*)d_in[7];
    const float* qnw  = (const float*)d_in[8];
    const float* knw  = (const float*)d_in[9];
    const float* gw   = (const float*)d_in[10];
    const float* w1   = (const float*)d_in[11];
    const float* w2   = (const float*)d_in[12];
    const float* w3   = (const float*)d_in[13];

    float* out0 = (float*)d_out;
    float* kout = out0 + (size_t)TD * HDIM;
    float* vout = kout + (size_t)TD * HKV * HDH;

    __half *hn, *yb, *tb, *qh, *kh, *vT;
    float *qb, *kp;
    cudaGetSymbolAddress((void**)&hn, g_hn);
    cudaGetSymbolAddress((void**)&qb, g_q);
    cudaGetSymbolAddress((void**)&kp, g_kproj);
    cudaGetSymbolAddress((void**)&qh, g_qh);
    cudaGetSymbolAddress((void**)&kh, g_kh);
    cudaGetSymbolAddress((void**)&vT, g_vT);
    cudaGetSymbolAddress((void**)&yb, g_y);
    cudaGetSymbolAddress((void**)&tb, g_t);

    cudaFuncSetAttribute(attn_h, cudaFuncAttributeMaxDynamicSharedMemorySize, ATT_SMEM);
    cudaFuncSetAttribute(gemm_tc, cudaFuncAttributeMaxDynamicSharedMemorySize, GEMM_SMEM);
    cudaFuncSetAttribute(qkv_tc, cudaFuncAttributeMaxDynamicSharedMemorySize, GEMM_SMEM);
    cudaFuncSetAttribute(moe1_tc, cudaFuncAttributeMaxDynamicSharedMemorySize, MOE1_SMEM);
    cudaFuncSetAttribute(moe2_tc, cudaFuncAttributeMaxDynamicSharedMemorySize, GEMM_SMEM);

    rmsnorm_k<<<TD, 256>>>(x, n1w, hn);
    qkv_tc<<<dim3(12, TD / 128), 256, GEMM_SMEM>>>(hn, wq, wk, wv, qb, kp, vout);
    qknorm_rope3_k<<<TD * (HQ + HKV) / 8, 256>>>(qb, kp, qnw, knw, freq, qh, kout, kh);
    vtrans_k<<<dim3(SD / 32, BD * HKV), 256>>>(vout, vT);
    attn_h<<<dim3(SD / 64, HQ, BD), 128, ATT_SMEM>>>(qh, kh, vT, yb);
    gemm_tc<<<dim3(HDIM / 128, TD / 128), 256, GEMM_SMEM>>>(yb, wo, out0, x, TD, HDIM, HDIM);
    rmsnorm_k<<<TD, 256>>>(out0, n2w, tb);
    gate_k<<<TD, 256>>>(tb, gw);
    moe1_tc<<<dim3(IDIM / 64, TD / 128, ED), 256, MOE1_SMEM>>>(tb, w1, w3);
    moe2_tc<<<dim3(HDIM / 128, TD / 128, ED), 256, GEMM_SMEM>>>(w2, out0);
}